// round 4
// baseline (speedup 1.0000x reference)
#include <cuda_runtime.h>
#include <math.h>
#include <stdint.h>

#define NN 50000
#define NE 800000
#define NG 256

// ---------------- scratch (static __device__, no allocs) ----------------
__device__ int   g_is64;
__device__ float g_deg [NN];
__device__ float g_dinv[NN];
__device__ float g_aggx[NN * 19];
__device__ float g_h1  [NN * 500];
__device__ float g_z   [NN * 400];   // Z2 (400) then Z3 (300)
__device__ float g_agg [NN * 400];   // agg buffer, reused
__device__ float g_h2  [NN * 400];
__device__ float g_h3  [NN * 300];
__device__ float g_gmax[NG * 300];
__device__ float g_m1  [NG * 200];
__device__ float g_m2  [NG * 100];

// Index accessor: handles both int32 and int64 index tensors.
__device__ __forceinline__ int IDX(const void* p, long long i, int is64) {
    return is64 ? (int)((const long long*)p)[i] : ((const int*)p)[i];
}

// ---------------- dtype detection ----------------
// If the buffer is really int32, interpreting as int64 fuses pairs of indices:
// value = lo + (hi << 32) with hi = the next int32 index (mostly nonzero),
// so some value lands outside [0, NN) with overwhelming probability.
__global__ void k_detect(const long long* ei) {
    if (threadIdx.x == 0 && blockIdx.x == 0) {
        int ok = 1;
        for (int i = 0; i < 1024; i++) {
            long long v = ei[i];
            if (v < 0 || v >= NN) { ok = 0; break; }
        }
        g_is64 = ok;
    }
}

// ---------------- small utility kernels ----------------
__global__ void k_zero_deg() {
    int i = blockIdx.x * blockDim.x + threadIdx.x;
    if (i < NN) g_deg[i] = 0.f;
}
__global__ void k_zero_gmax() {
    int i = blockIdx.x * blockDim.x + threadIdx.x;
    if (i < NG * 300) g_gmax[i] = 0.f;   // values are >=0 post-ReLU
}
__global__ void k_deg(const void* __restrict__ ei) {
    int i = blockIdx.x * blockDim.x + threadIdx.x;
    if (i < NE) {
        int is64 = g_is64;
        int t = IDX(ei, (long long)NE + i, is64);   // dst = row 1
        atomicAdd(&g_deg[t], 1.0f);
    }
}
__global__ void k_dinv() {
    int i = blockIdx.x * blockDim.x + threadIdx.x;
    if (i < NN) g_dinv[i] = rsqrtf(g_deg[i] + 1.0f);
}

// ---------------- layer 1: aggregate at dim 19, then GEMM ----------------
__global__ void k_aggx_init(const float* __restrict__ x) {
    int i = blockIdx.x * blockDim.x + threadIdx.x;
    if (i < NN * 19) {
        int n = i / 19;
        float d = g_dinv[n];
        g_aggx[i] = x[i] * d * d;
    }
}
__global__ void k_scatter_x(const float* __restrict__ x,
                            const void* __restrict__ ei) {
    int i = blockIdx.x * blockDim.x + threadIdx.x;
    if (i < NE * 19) {
        int e = i / 19;
        int f = i - e * 19;
        int is64 = g_is64;
        int s = IDX(ei, e, is64);
        int t = IDX(ei, (long long)NE + e, is64);
        float c = g_dinv[s] * g_dinv[t];
        atomicAdd(&g_aggx[t * 19 + f], x[s * 19 + f] * c);
    }
}
// H1 = relu(aggx @ W1 + b1), W1 cached fully in smem (19x500 = 38 KB)
__global__ void k_gemm1(const float* __restrict__ W1, const float* __restrict__ b1) {
    __shared__ float sW[19 * 500];
    __shared__ float sx[32 * 19];
    int t = threadIdx.x;                 // 256 threads
    for (int i = t; i < 19 * 500; i += 256) sW[i] = W1[i];
    int n0 = blockIdx.x * 32;
    for (int i = t; i < 32 * 19; i += 256) {
        int r = i / 19;
        int n = n0 + r;
        sx[i] = (n < NN) ? g_aggx[n * 19 + (i % 19)] : 0.f;
    }
    __syncthreads();
    for (int i = t; i < 32 * 500; i += 256) {
        int r = i / 500, c = i - r * 500;
        int n = n0 + r;
        if (n < NN) {
            float acc = b1[c];
#pragma unroll
            for (int k = 0; k < 19; k++) acc += sx[r * 19 + k] * sW[k * 500 + c];
            g_h1[(size_t)n * 500 + c] = fmaxf(acc, 0.f);
        }
    }
}

// ---------------- tiled SGEMM, epilogue writes Z and agg-init = Z*dinv^2 ----------------
// Z = A[MxK] @ W[KxN], row-major.  BM=BN=128, BK=8, 256 threads, 8x8 per thread.
// layer==2: A=g_h1  (K=500,N=400) ; layer==3: A=g_h2 (K=400,N=300)
__global__ void __launch_bounds__(256)
k_sgemm_fuse(const float* __restrict__ B, int layer, int M, int N, int K) {
    const float* __restrict__ A = (layer == 2) ? g_h1 : g_h2;
    float* __restrict__ C  = g_z;
    float* __restrict__ C2 = g_agg;

    __shared__ float As[8][128];
    __shared__ float Bs[8][128];
    int t  = threadIdx.x;
    int m0 = blockIdx.y * 128, n0 = blockIdx.x * 128;
    int tx = t & 15, ty = t >> 4;

    float acc[8][8];
#pragma unroll
    for (int i = 0; i < 8; i++)
#pragma unroll
        for (int j = 0; j < 8; j++) acc[i][j] = 0.f;

    int arow = t >> 1;        // 0..127
    int acol = (t & 1) * 4;   // 0 or 4
    int brow = t >> 5;        // 0..7
    int bcol = (t & 31) * 4;  // 0..124
    const float* Aptr = A + (size_t)(m0 + arow) * K;
    bool arow_ok = (m0 + arow) < M;
    bool bcol_ok = (n0 + bcol) < N;

    for (int k0 = 0; k0 < K; k0 += 8) {
        float4 av = make_float4(0.f, 0.f, 0.f, 0.f);
        if (arow_ok && (k0 + acol) < K)
            av = *(const float4*)(Aptr + k0 + acol);
        As[acol + 0][arow] = av.x;
        As[acol + 1][arow] = av.y;
        As[acol + 2][arow] = av.z;
        As[acol + 3][arow] = av.w;

        float4 bv = make_float4(0.f, 0.f, 0.f, 0.f);
        if ((k0 + brow) < K && bcol_ok)
            bv = *(const float4*)(B + (size_t)(k0 + brow) * N + n0 + bcol);
        *(float4*)&Bs[brow][bcol] = bv;
        __syncthreads();

#pragma unroll
        for (int kk = 0; kk < 8; kk++) {
            float4 a0 = *(float4*)&As[kk][ty * 8];
            float4 a1 = *(float4*)&As[kk][ty * 8 + 4];
            float4 b0 = *(float4*)&Bs[kk][tx * 8];
            float4 b1 = *(float4*)&Bs[kk][tx * 8 + 4];
            float a[8] = {a0.x, a0.y, a0.z, a0.w, a1.x, a1.y, a1.z, a1.w};
            float b[8] = {b0.x, b0.y, b0.z, b0.w, b1.x, b1.y, b1.z, b1.w};
#pragma unroll
            for (int i = 0; i < 8; i++)
#pragma unroll
                for (int j = 0; j < 8; j++) acc[i][j] += a[i] * b[j];
        }
        __syncthreads();
    }

#pragma unroll
    for (int i = 0; i < 8; i++) {
        int row = m0 + ty * 8 + i;
        if (row >= M) continue;
        float d  = g_dinv[row];
        float dd = d * d;
#pragma unroll
        for (int j = 0; j < 8; j++) {
            int col = n0 + tx * 8 + j;
            if (col < N) {
                float v = acc[i][j];
                C [(size_t)row * N + col] = v;
                C2[(size_t)row * N + col] = v * dd;
            }
        }
    }
}

// ---------------- edge scatter at dim F (one warp per edge, float4 reads) ----------------
__global__ void k_scatter(const void* __restrict__ ei, int F) {
    int warp = (blockIdx.x * blockDim.x + threadIdx.x) >> 5;
    int lane = threadIdx.x & 31;
    if (warp >= NE) return;
    int is64 = g_is64;
    int s = IDX(ei, warp, is64);
    int t = IDX(ei, (long long)NE + warp, is64);
    float c = g_dinv[s] * g_dinv[t];
    const float4* zr = (const float4*)(g_z + (size_t)s * F);
    float* ar = g_agg + (size_t)t * F;
    int nf4 = F >> 2;
    for (int i = lane; i < nf4; i += 32) {
        float4 v = zr[i];
        atomicAdd(&ar[i * 4 + 0], v.x * c);
        atomicAdd(&ar[i * 4 + 1], v.y * c);
        atomicAdd(&ar[i * 4 + 2], v.z * c);
        atomicAdd(&ar[i * 4 + 3], v.w * c);
    }
}

__global__ void k_bias_relu(const float* __restrict__ b, int layer, int total, int F) {
    float* __restrict__ H = (layer == 2) ? g_h2 : g_h3;
    int i = blockIdx.x * blockDim.x + threadIdx.x;
    if (i < total) {
        int c = i % F;
        H[i] = fmaxf(g_agg[i] + b[c], 0.f);
    }
}

// ---------------- graph max-pool (uint atomicMax valid for >=0 floats) ----------------
__global__ void k_segmax(const void* __restrict__ batch) {
    int i = blockIdx.x * blockDim.x + threadIdx.x;
    if (i < NN * 300) {
        int n = i / 300, f = i - n * 300;
        int b = IDX(batch, n, g_is64);
        atomicMax((unsigned int*)&g_gmax[b * 300 + f], __float_as_uint(g_h3[i]));
    }
}

// ---------------- MLP head ----------------
// sel==0: g_m1 = relu(g_gmax @ Wl1 + bl1) ; sel==1: g_m2 = relu(g_m1 @ Wl2 + bl2)
__global__ void k_mlp(const float* __restrict__ W, const float* __restrict__ b,
                      int sel, int M, int N, int K) {
    const float* __restrict__ A = (sel == 0) ? g_gmax : g_m1;
    float* __restrict__ C       = (sel == 0) ? g_m1   : g_m2;
    int i = blockIdx.x * blockDim.x + threadIdx.x;
    if (i < M * N) {
        int m = i / N, n = i - m * N;
        float acc = b[n];
        const float* ar = A + (size_t)m * K;
#pragma unroll 4
        for (int k = 0; k < K; k++) acc += ar[k] * W[(size_t)k * N + n];
        C[i] = fmaxf(acc, 0.f);
    }
}

// logits = m2 @ Wl3 + bl3, then softmax over graph axis (axis 0, per column)
__global__ void k_final(const float* __restrict__ Wl3, const float* __restrict__ bl3,
                        float* __restrict__ out) {
    __shared__ float sl[NG * 6];
    __shared__ float smax[6], ssum[6];
    int t = threadIdx.x;  // 256 threads, one per graph
    float acc[6];
#pragma unroll
    for (int j = 0; j < 6; j++) acc[j] = bl3[j];
    const float* mr = &g_m2[t * 100];
    for (int k = 0; k < 100; k++) {
        float a = mr[k];
#pragma unroll
        for (int j = 0; j < 6; j++) acc[j] += a * Wl3[k * 6 + j];
    }
#pragma unroll
    for (int j = 0; j < 6; j++) sl[t * 6 + j] = acc[j];
    __syncthreads();
    if (t < 6) {
        float mx = -3.4e38f;
        for (int r = 0; r < NG; r++) mx = fmaxf(mx, sl[r * 6 + t]);
        float s = 0.f;
        for (int r = 0; r < NG; r++) s += expf(sl[r * 6 + t] - mx);
        smax[t] = mx;
        ssum[t] = s;
    }
    __syncthreads();
#pragma unroll
    for (int j = 0; j < 6; j++)
        out[t * 6 + j] = expf(sl[t * 6 + j] - smax[j]) / ssum[j];
}

// ---------------- launch ----------------
extern "C" void kernel_launch(void* const* d_in, const int* in_sizes, int n_in,
                              void* d_out, int out_size) {
    const float* x     = (const float*)d_in[0];
    const void*  ei    = d_in[1];
    const void*  batch = d_in[2];
    const float* W1  = (const float*)d_in[3];  const float* b1  = (const float*)d_in[4];
    const float* W2  = (const float*)d_in[5];  const float* b2  = (const float*)d_in[6];
    const float* W3  = (const float*)d_in[7];  const float* b3  = (const float*)d_in[8];
    const float* Wl1 = (const float*)d_in[9];  const float* bl1 = (const float*)d_in[10];
    const float* Wl2 = (const float*)d_in[11]; const float* bl2 = (const float*)d_in[12];
    const float* Wl3 = (const float*)d_in[13]; const float* bl3 = (const float*)d_in[14];
    float* out = (float*)d_out;

    // dtype detect, degrees + normalization
    k_detect<<<1, 32>>>((const long long*)ei);
    k_zero_deg<<<(NN + 255) / 256, 256>>>();
    k_deg<<<(NE + 255) / 256, 256>>>(ei);
    k_dinv<<<(NN + 255) / 256, 256>>>();

    // layer 1: aggregate at dim 19, then GEMM(+bias+relu)
    k_aggx_init<<<(NN * 19 + 255) / 256, 256>>>(x);
    k_scatter_x<<<(NE * 19 + 255) / 256, 256>>>(x, ei);
    k_gemm1<<<(NN + 31) / 32, 256>>>(W1, b1);

    // layer 2: Z2 = H1 @ W2 (epilogue writes agg-init), scatter, bias+relu
    {
        dim3 grid((400 + 127) / 128, (NN + 127) / 128);
        k_sgemm_fuse<<<grid, 256>>>(W2, 2, NN, 400, 500);
    }
    k_scatter<<<(NE * 32 + 255) / 256, 256>>>(ei, 400);
    k_bias_relu<<<(NN * 400 + 255) / 256, 256>>>(b2, 2, NN * 400, 400);

    // layer 3
    {
        dim3 grid((300 + 127) / 128, (NN + 127) / 128);
        k_sgemm_fuse<<<grid, 256>>>(W3, 3, NN, 300, 400);
    }
    k_scatter<<<(NE * 32 + 255) / 256, 256>>>(ei, 300);
    k_bias_relu<<<(NN * 300 + 255) / 256, 256>>>(b3, 3, NN * 300, 300);

    // graph max-pool
    k_zero_gmax<<<(NG * 300 + 255) / 256, 256>>>();
    k_segmax<<<(NN * 300 + 255) / 256, 256>>>(batch);

    // MLP head + softmax over graphs
    k_mlp<<<(NG * 200 + 255) / 256, 256>>>(Wl1, bl1, 0, NG, 200, 300);
    k_mlp<<<(NG * 100 + 255) / 256, 256>>>(Wl2, bl2, 1, NG, 100, 200);
    k_final<<<1, 256>>>(Wl3, bl3, out);
}

// round 5
// speedup vs baseline: 1.7508x; 1.7508x over previous
#include <cuda_runtime.h>
#include <math.h>
#include <stdint.h>

#define NN 50000
#define NE 800000
#define NG 256

// ---------------- scratch (static __device__, no allocs) ----------------
__device__ int   g_is64;
__device__ int   g_degi[NN];
__device__ int   g_off [NN];
__device__ int   g_cnt [NN];
__device__ int   g_esrc[NE];
__device__ float g_ecoef[NE];
__device__ float g_dinv[NN];
__device__ float g_aggx[NN * 19];
__device__ float g_h1  [NN * 500];
__device__ float g_z   [NN * 400];   // Z2 (400) then Z3 (300)
__device__ float g_h2  [NN * 400];
__device__ float g_h3  [NN * 300];
__device__ float g_gmax[NG * 300];
__device__ float g_m1  [NG * 200];
__device__ float g_m2  [NG * 100];

// Index accessor: handles both int32 and int64 index tensors.
__device__ __forceinline__ int IDX(const void* p, long long i, int is64) {
    return is64 ? (int)((const long long*)p)[i] : ((const int*)p)[i];
}

// ---------------- dtype detection (int32 vs int64 index tensors) ----------------
__global__ void k_detect(const long long* ei) {
    if (threadIdx.x == 0 && blockIdx.x == 0) {
        int ok = 1;
        for (int i = 0; i < 1024; i++) {
            long long v = ei[i];
            if (v < 0 || v >= NN) { ok = 0; break; }
        }
        g_is64 = ok;
    }
}

// ---------------- degree / normalization / CSR build ----------------
__global__ void k_zero_int() {
    int i = blockIdx.x * blockDim.x + threadIdx.x;
    if (i < NN) { g_degi[i] = 0; g_cnt[i] = 0; }
}
__global__ void k_deg(const void* __restrict__ ei) {
    int i = blockIdx.x * blockDim.x + threadIdx.x;
    if (i < NE) {
        int t = IDX(ei, (long long)NE + i, g_is64);   // dst = row 1
        atomicAdd(&g_degi[t], 1);
    }
}
__global__ void k_dinv() {
    int i = blockIdx.x * blockDim.x + threadIdx.x;
    if (i < NN) g_dinv[i] = rsqrtf((float)g_degi[i] + 1.0f);
}
// exclusive prefix sum of g_degi -> g_off (single block, 1024 threads)
__global__ void k_scan() {
    __shared__ int ssum[1024];
    const int CH = (NN + 1023) / 1024;   // 49
    int t = threadIdx.x;
    int base = t * CH;
    int loc = 0;
    for (int i = 0; i < CH; i++) { int n = base + i; if (n < NN) loc += g_degi[n]; }
    ssum[t] = loc;
    __syncthreads();
    for (int off = 1; off < 1024; off <<= 1) {
        int v = (t >= off) ? ssum[t - off] : 0;
        __syncthreads();
        ssum[t] += v;
        __syncthreads();
    }
    int run = (t == 0) ? 0 : ssum[t - 1];
    for (int i = 0; i < CH; i++) {
        int n = base + i;
        if (n < NN) { g_off[n] = run; run += g_degi[n]; }
    }
}
__global__ void k_fill(const void* __restrict__ ei) {
    int e = blockIdx.x * blockDim.x + threadIdx.x;
    if (e < NE) {
        int is64 = g_is64;
        int s = IDX(ei, e, is64);
        int t = IDX(ei, (long long)NE + e, is64);
        int pos = atomicAdd(&g_cnt[t], 1);
        int idx = g_off[t] + pos;
        g_esrc[idx]  = s;
        g_ecoef[idx] = g_dinv[s] * g_dinv[t];
    }
}

// ---------------- layer 1: gather-aggregate at dim 19 ----------------
__global__ void k_gather1(const float* __restrict__ x) {
    int node = blockIdx.x * (blockDim.x >> 5) + (threadIdx.x >> 5);
    int lane = threadIdx.x & 31;
    if (node >= NN) return;
    float d = g_dinv[node], dd = d * d;
    float acc = 0.f;
    if (lane < 19) acc = x[(size_t)node * 19 + lane] * dd;
    int beg = g_off[node], end = beg + g_degi[node];
    for (int e = beg; e < end; e++) {
        int s = g_esrc[e];
        float c = g_ecoef[e];
        if (lane < 19) acc += x[(size_t)s * 19 + lane] * c;
    }
    if (lane < 19) g_aggx[(size_t)node * 19 + lane] = acc;
}

// H1 = relu(aggx @ W1 + b1), W1 cached fully in smem (19x500 = 38 KB)
__global__ void k_gemm1(const float* __restrict__ W1, const float* __restrict__ b1) {
    __shared__ float sW[19 * 500];
    __shared__ float sx[32 * 19];
    int t = threadIdx.x;                 // 256 threads
    for (int i = t; i < 19 * 500; i += 256) sW[i] = W1[i];
    int n0 = blockIdx.x * 32;
    for (int i = t; i < 32 * 19; i += 256) {
        int r = i / 19;
        int n = n0 + r;
        sx[i] = (n < NN) ? g_aggx[n * 19 + (i % 19)] : 0.f;
    }
    __syncthreads();
    for (int i = t; i < 32 * 500; i += 256) {
        int r = i / 500, c = i - r * 500;
        int n = n0 + r;
        if (n < NN) {
            float acc = b1[c];
#pragma unroll
            for (int k = 0; k < 19; k++) acc += sx[r * 19 + k] * sW[k * 500 + c];
            g_h1[(size_t)n * 500 + c] = fmaxf(acc, 0.f);
        }
    }
}

// ---------------- tiled SGEMM: g_z = A @ W ----------------
// BM=BN=128, BK=8, 256 threads, 8x8 per thread. layer 2: A=g_h1; layer 3: A=g_h2.
__global__ void __launch_bounds__(256)
k_sgemm(const float* __restrict__ B, int layer, int M, int N, int K) {
    const float* __restrict__ A = (layer == 2) ? g_h1 : g_h2;
    float* __restrict__ C = g_z;

    __shared__ float As[8][128];
    __shared__ float Bs[8][128];
    int t  = threadIdx.x;
    int m0 = blockIdx.y * 128, n0 = blockIdx.x * 128;
    int tx = t & 15, ty = t >> 4;

    float acc[8][8];
#pragma unroll
    for (int i = 0; i < 8; i++)
#pragma unroll
        for (int j = 0; j < 8; j++) acc[i][j] = 0.f;

    int arow = t >> 1;        // 0..127
    int acol = (t & 1) * 4;   // 0 or 4
    int brow = t >> 5;        // 0..7
    int bcol = (t & 31) * 4;  // 0..124
    const float* Aptr = A + (size_t)(m0 + arow) * K;
    bool arow_ok = (m0 + arow) < M;
    bool bcol_ok = (n0 + bcol) < N;

    for (int k0 = 0; k0 < K; k0 += 8) {
        float4 av = make_float4(0.f, 0.f, 0.f, 0.f);
        if (arow_ok && (k0 + acol) < K)
            av = *(const float4*)(Aptr + k0 + acol);
        As[acol + 0][arow] = av.x;
        As[acol + 1][arow] = av.y;
        As[acol + 2][arow] = av.z;
        As[acol + 3][arow] = av.w;

        float4 bv = make_float4(0.f, 0.f, 0.f, 0.f);
        if ((k0 + brow) < K && bcol_ok)
            bv = *(const float4*)(B + (size_t)(k0 + brow) * N + n0 + bcol);
        *(float4*)&Bs[brow][bcol] = bv;
        __syncthreads();

#pragma unroll
        for (int kk = 0; kk < 8; kk++) {
            float4 a0 = *(float4*)&As[kk][ty * 8];
            float4 a1 = *(float4*)&As[kk][ty * 8 + 4];
            float4 b0 = *(float4*)&Bs[kk][tx * 8];
            float4 b1 = *(float4*)&Bs[kk][tx * 8 + 4];
            float a[8] = {a0.x, a0.y, a0.z, a0.w, a1.x, a1.y, a1.z, a1.w};
            float b[8] = {b0.x, b0.y, b0.z, b0.w, b1.x, b1.y, b1.z, b1.w};
#pragma unroll
            for (int i = 0; i < 8; i++)
#pragma unroll
                for (int j = 0; j < 8; j++) acc[i][j] += a[i] * b[j];
        }
        __syncthreads();
    }

#pragma unroll
    for (int i = 0; i < 8; i++) {
        int row = m0 + ty * 8 + i;
        if (row >= M) continue;
#pragma unroll
        for (int j = 0; j < 8; j++) {
            int col = n0 + tx * 8 + j;
            if (col < N) C[(size_t)row * N + col] = acc[i][j];
        }
    }
}

// ---------------- CSR gather-aggregate + bias + relu (no atomics) ----------------
// H[node] = relu( z[node]*dinv^2 + sum_in z[src]*coef + bias )
template<int F>
__global__ void __launch_bounds__(256)
k_gather(const float* __restrict__ bias, float* __restrict__ H) {
    constexpr int F4 = F / 4;
    constexpr int NR = (F4 + 31) / 32;
    int node = blockIdx.x * (blockDim.x >> 5) + (threadIdx.x >> 5);
    int lane = threadIdx.x & 31;
    if (node >= NN) return;

    float d = g_dinv[node], dd = d * d;
    const float4* z4 = (const float4*)g_z;

    float4 acc[NR];
#pragma unroll
    for (int r = 0; r < NR; r++) {
        int f = lane + 32 * r;
        if (f < F4) {
            float4 v = z4[(size_t)node * F4 + f];
            acc[r] = make_float4(v.x * dd, v.y * dd, v.z * dd, v.w * dd);
        } else acc[r] = make_float4(0.f, 0.f, 0.f, 0.f);
    }

    int beg = g_off[node], end = beg + g_degi[node];
    for (int e = beg; e < end; e++) {
        int s = g_esrc[e];
        float c = g_ecoef[e];
        const float4* zs = z4 + (size_t)s * F4;
#pragma unroll
        for (int r = 0; r < NR; r++) {
            int f = lane + 32 * r;
            if (f < F4) {
                float4 v = zs[f];
                acc[r].x += v.x * c;
                acc[r].y += v.y * c;
                acc[r].z += v.z * c;
                acc[r].w += v.w * c;
            }
        }
    }

    float4* h4 = (float4*)H;
    const float4* b4 = (const float4*)bias;
#pragma unroll
    for (int r = 0; r < NR; r++) {
        int f = lane + 32 * r;
        if (f < F4) {
            float4 b = b4[f];
            h4[(size_t)node * F4 + f] = make_float4(
                fmaxf(acc[r].x + b.x, 0.f), fmaxf(acc[r].y + b.y, 0.f),
                fmaxf(acc[r].z + b.z, 0.f), fmaxf(acc[r].w + b.w, 0.f));
        }
    }
}

// ---------------- graph max-pool (uint atomicMax valid for >=0 floats) ----------------
__global__ void k_zero_gmax() {
    int i = blockIdx.x * blockDim.x + threadIdx.x;
    if (i < NG * 300) g_gmax[i] = 0.f;   // values are >=0 post-ReLU
}
__global__ void k_segmax(const void* __restrict__ batch) {
    int i = blockIdx.x * blockDim.x + threadIdx.x;
    if (i < NN * 300) {
        int n = i / 300, f = i - n * 300;
        int b = IDX(batch, n, g_is64);
        atomicMax((unsigned int*)&g_gmax[b * 300 + f], __float_as_uint(g_h3[i]));
    }
}

// ---------------- MLP head ----------------
__global__ void k_mlp(const float* __restrict__ W, const float* __restrict__ b,
                      int sel, int M, int N, int K) {
    const float* __restrict__ A = (sel == 0) ? g_gmax : g_m1;
    float* __restrict__ C       = (sel == 0) ? g_m1   : g_m2;
    int i = blockIdx.x * blockDim.x + threadIdx.x;
    if (i < M * N) {
        int m = i / N, n = i - m * N;
        float acc = b[n];
        const float* ar = A + (size_t)m * K;
#pragma unroll 4
        for (int k = 0; k < K; k++) acc += ar[k] * W[(size_t)k * N + n];
        C[i] = fmaxf(acc, 0.f);
    }
}

// logits = m2 @ Wl3 + bl3, then softmax over graph axis (axis 0, per column)
__global__ void k_final(const float* __restrict__ Wl3, const float* __restrict__ bl3,
                        float* __restrict__ out) {
    __shared__ float sl[NG * 6];
    __shared__ float smax[6], ssum[6];
    int t = threadIdx.x;  // 256 threads, one per graph
    float acc[6];
#pragma unroll
    for (int j = 0; j < 6; j++) acc[j] = bl3[j];
    const float* mr = &g_m2[t * 100];
    for (int k = 0; k < 100; k++) {
        float a = mr[k];
#pragma unroll
        for (int j = 0; j < 6; j++) acc[j] += a * Wl3[k * 6 + j];
    }
#pragma unroll
    for (int j = 0; j < 6; j++) sl[t * 6 + j] = acc[j];
    __syncthreads();
    if (t < 6) {
        float mx = -3.4e38f;
        for (int r = 0; r < NG; r++) mx = fmaxf(mx, sl[r * 6 + t]);
        float s = 0.f;
        for (int r = 0; r < NG; r++) s += expf(sl[r * 6 + t] - mx);
        smax[t] = mx;
        ssum[t] = s;
    }
    __syncthreads();
#pragma unroll
    for (int j = 0; j < 6; j++)
        out[t * 6 + j] = expf(sl[t * 6 + j] - smax[j]) / ssum[j];
}

// ---------------- launch ----------------
extern "C" void kernel_launch(void* const* d_in, const int* in_sizes, int n_in,
                              void* d_out, int out_size) {
    const float* x     = (const float*)d_in[0];
    const void*  ei    = d_in[1];
    const void*  batch = d_in[2];
    const float* W1  = (const float*)d_in[3];  const float* b1  = (const float*)d_in[4];
    const float* W2  = (const float*)d_in[5];  const float* b2  = (const float*)d_in[6];
    const float* W3  = (const float*)d_in[7];  const float* b3  = (const float*)d_in[8];
    const float* Wl1 = (const float*)d_in[9];  const float* bl1 = (const float*)d_in[10];
    const float* Wl2 = (const float*)d_in[11]; const float* bl2 = (const float*)d_in[12];
    const float* Wl3 = (const float*)d_in[13]; const float* bl3 = (const float*)d_in[14];
    float* out = (float*)d_out;

    float *p_h2, *p_h3;
    cudaGetSymbolAddress((void**)&p_h2, g_h2);
    cudaGetSymbolAddress((void**)&p_h3, g_h3);

    // dtype detect, degree, dinv, CSR build
    k_detect<<<1, 32>>>((const long long*)ei);
    k_zero_int<<<(NN + 255) / 256, 256>>>();
    k_deg<<<(NE + 255) / 256, 256>>>(ei);
    k_dinv<<<(NN + 255) / 256, 256>>>();
    k_scan<<<1, 1024>>>();
    k_fill<<<(NE + 255) / 256, 256>>>(ei);

    // layer 1: gather at dim 19, then GEMM(+bias+relu)
    k_gather1<<<(NN * 32 + 255) / 256, 256>>>(x);
    k_gemm1<<<(NN + 31) / 32, 256>>>(W1, b1);

    // layer 2: Z2 = H1 @ W2, then CSR gather + bias + relu -> H2
    {
        dim3 grid((400 + 127) / 128, (NN + 127) / 128);
        k_sgemm<<<grid, 256>>>(W2, 2, NN, 400, 500);
    }
    k_gather<400><<<(NN * 32 + 255) / 256, 256>>>(b2, p_h2);

    // layer 3
    {
        dim3 grid((300 + 127) / 128, (NN + 127) / 128);
        k_sgemm<<<grid, 256>>>(W3, 3, NN, 300, 400);
    }
    k_gather<300><<<(NN * 32 + 255) / 256, 256>>>(b3, p_h3);

    // graph max-pool
    k_zero_gmax<<<(NG * 300 + 255) / 256, 256>>>();
    k_segmax<<<(NN * 300 + 255) / 256, 256>>>(batch);

    // MLP head + softmax over graphs
    k_mlp<<<(NG * 200 + 255) / 256, 256>>>(Wl1, bl1, 0, NG, 200, 300);
    k_mlp<<<(NG * 100 + 255) / 256, 256>>>(Wl2, bl2, 1, NG, 100, 200);
    k_final<<<1, 256>>>(Wl3, bl3, out);
}

// round 10
// speedup vs baseline: 2.5869x; 1.4776x over previous
#include <cuda_runtime.h>
#include <math.h>
#include <stdint.h>
#include <mma.h>
using namespace nvcuda;

#define NN 50000
#define NE 800000
#define NG 256

#define MP 50048          // NN padded to 128-tile
#define ZS 512            // Z / H1 column stride (padded)

// ---------------- scratch (static __device__, zero-init, no allocs) ----------------
__device__ int   g_is64;
__device__ int   g_degi[NN];
__device__ int   g_off [NN];
__device__ int   g_cnt [NN];
__device__ int   g_esrc[NE];
__device__ float g_ecoef[NE];
__device__ float g_dinv[NN];
__device__ float g_aggx[NN * 19];
__device__ float g_h1  [MP * ZS];     // padded: rows>=NN and cols>=500 stay zero
__device__ float g_z   [MP * ZS];     // GEMM output, stride ZS
__device__ float g_h2  [MP * 400];    // padded rows stay zero
__device__ float g_h3  [NN * 300];
__device__ float g_w2p [512 * 512];   // W2 padded (pad stays zero)
__device__ float g_w3p [400 * 384];   // W3 padded (pad stays zero)
__device__ float g_gmax[NG * 300];
__device__ float g_m1  [NG * 200];
__device__ float g_m2  [NG * 100];

// Index accessor: handles both int32 and int64 index tensors.
__device__ __forceinline__ int IDX(const void* p, long long i, int is64) {
    return is64 ? (int)((const long long*)p)[i] : ((const int*)p)[i];
}

// ---------------- dtype detection (int32 vs int64 index tensors) ----------------
__global__ void k_detect(const long long* ei) {
    if (threadIdx.x == 0 && blockIdx.x == 0) {
        int ok = 1;
        for (int i = 0; i < 1024; i++) {
            long long v = ei[i];
            if (v < 0 || v >= NN) { ok = 0; break; }
        }
        g_is64 = ok;
    }
}

// ---------------- degree / normalization / CSR build ----------------
__global__ void k_zero_int() {
    int i = blockIdx.x * blockDim.x + threadIdx.x;
    if (i < NN) { g_degi[i] = 0; g_cnt[i] = 0; }
}
__global__ void k_deg(const void* __restrict__ ei) {
    int i = blockIdx.x * blockDim.x + threadIdx.x;
    if (i < NE) {
        int t = IDX(ei, (long long)NE + i, g_is64);   // dst = row 1
        atomicAdd(&g_degi[t], 1);
    }
}
__global__ void k_dinv() {
    int i = blockIdx.x * blockDim.x + threadIdx.x;
    if (i < NN) g_dinv[i] = rsqrtf((float)g_degi[i] + 1.0f);
}
// exclusive prefix sum of g_degi -> g_off (single block, 1024 threads)
__global__ void k_scan() {
    __shared__ int ssum[1024];
    const int CH = (NN + 1023) / 1024;   // 49
    int t = threadIdx.x;
    int base = t * CH;
    int loc = 0;
    for (int i = 0; i < CH; i++) { int n = base + i; if (n < NN) loc += g_degi[n]; }
    ssum[t] = loc;
    __syncthreads();
    for (int off = 1; off < 1024; off <<= 1) {
        int v = (t >= off) ? ssum[t - off] : 0;
        __syncthreads();
        ssum[t] += v;
        __syncthreads();
    }
    int run = (t == 0) ? 0 : ssum[t - 1];
    for (int i = 0; i < CH; i++) {
        int n = base + i;
        if (n < NN) { g_off[n] = run; run += g_degi[n]; }
    }
}
__global__ void k_fill(const void* __restrict__ ei) {
    int e = blockIdx.x * blockDim.x + threadIdx.x;
    if (e < NE) {
        int is64 = g_is64;
        int s = IDX(ei, e, is64);
        int t = IDX(ei, (long long)NE + e, is64);
        int pos = atomicAdd(&g_cnt[t], 1);
        int idx = g_off[t] + pos;
        g_esrc[idx]  = s;
        g_ecoef[idx] = g_dinv[s] * g_dinv[t];
    }
}

// ---------------- weight padding (valid region only; pad stays zero) ----------------
__global__ void k_wpad(const float* __restrict__ W2, const float* __restrict__ W3) {
    int i = blockIdx.x * blockDim.x + threadIdx.x;
    if (i < 500 * 400) {
        int k = i / 400, n = i - k * 400;
        g_w2p[k * 512 + n] = W2[i];
    }
    int j = i - 500 * 400;
    if (j >= 0 && j < 400 * 300) {
        int k = j / 300, n = j - k * 300;
        g_w3p[k * 384 + n] = W3[j];
    }
}

// ---------------- layer 1: gather-aggregate at dim 19 ----------------
__global__ void k_gather1(const float* __restrict__ x) {
    int node = blockIdx.x * (blockDim.x >> 5) + (threadIdx.x >> 5);
    int lane = threadIdx.x & 31;
    if (node >= NN) return;
    float d = g_dinv[node], dd = d * d;
    float acc = 0.f;
    if (lane < 19) acc = x[(size_t)node * 19 + lane] * dd;
    int beg = g_off[node], end = beg + g_degi[node];
    for (int e = beg; e < end; e++) {
        int s = g_esrc[e];
        float c = g_ecoef[e];
        if (lane < 19) acc += x[(size_t)s * 19 + lane] * c;
    }
    if (lane < 19) g_aggx[(size_t)node * 19 + lane] = acc;
}

// H1 = relu(aggx @ W1 + b1), W1 cached fully in smem (19x500 = 38 KB)
__global__ void k_gemm1(const float* __restrict__ W1, const float* __restrict__ b1) {
    __shared__ float sW[19 * 500];
    __shared__ float sx[32 * 19];
    int t = threadIdx.x;                 // 256 threads
    for (int i = t; i < 19 * 500; i += 256) sW[i] = W1[i];
    int n0 = blockIdx.x * 32;
    for (int i = t; i < 32 * 19; i += 256) {
        int r = i / 19;
        int n = n0 + r;
        sx[i] = (n < NN) ? g_aggx[n * 19 + (i % 19)] : 0.f;
    }
    __syncthreads();
    for (int i = t; i < 32 * 500; i += 256) {
        int r = i / 500, c = i - r * 500;
        int n = n0 + r;
        if (n < NN) {
            float acc = b1[c];
#pragma unroll
            for (int k = 0; k < 19; k++) acc += sx[r * 19 + k] * sW[k * 500 + c];
            g_h1[(size_t)n * ZS + c] = fmaxf(acc, 0.f);
        }
    }
}

// ---------------- tf32 WMMA GEMM: C[MPxN] = A @ B, all tiles full (padded) ----------------
// BM=128, BN=128, BK=16, 256 threads (8 warps: 2x4), warp tile 64x32.
__global__ void __launch_bounds__(256)
k_wgemm(const float* __restrict__ A, const float* __restrict__ B,
        float* __restrict__ C, int lda, int ldb, int ldc, int K) {
    __shared__ float As[128][24];
    __shared__ float Bs[16][136];
    int t = threadIdx.x;
    int warp = t >> 5;
    int wy = warp >> 2;      // 0..1
    int wx = warp & 3;       // 0..3
    size_t m0 = (size_t)blockIdx.y * 128;
    int n0 = blockIdx.x * 128;

    wmma::fragment<wmma::accumulator, 16, 16, 8, float> acc[4][2];
#pragma unroll
    for (int i = 0; i < 4; i++)
#pragma unroll
        for (int j = 0; j < 2; j++) wmma::fill_fragment(acc[i][j], 0.f);

    for (int k0 = 0; k0 < K; k0 += 16) {
#pragma unroll
        for (int r = 0; r < 2; r++) {           // A tile 128x16 = 512 float4
            int id = t + r * 256;
            int row = id >> 2, c4 = (id & 3) * 4;
            float4 v = *(const float4*)(A + (m0 + row) * lda + k0 + c4);
            As[row][c4 + 0] = v.x; As[row][c4 + 1] = v.y;
            As[row][c4 + 2] = v.z; As[row][c4 + 3] = v.w;
        }
#pragma unroll
        for (int r = 0; r < 2; r++) {           // B tile 16x128 = 512 float4
            int id = t + r * 256;
            int row = id >> 5, c4 = (id & 31) * 4;
            float4 v = *(const float4*)(B + (size_t)(k0 + row) * ldb + n0 + c4);
            Bs[row][c4 + 0] = v.x; Bs[row][c4 + 1] = v.y;
            Bs[row][c4 + 2] = v.z; Bs[row][c4 + 3] = v.w;
        }
        __syncthreads();

#pragma unroll
        for (int kk = 0; kk < 16; kk += 8) {
            wmma::fragment<wmma::matrix_a, 16, 16, 8, wmma::precision::tf32, wmma::row_major> af[4];
            wmma::fragment<wmma::matrix_b, 16, 16, 8, wmma::precision::tf32, wmma::row_major> bf[2];
#pragma unroll
            for (int i = 0; i < 4; i++) {
                wmma::load_matrix_sync(af[i], &As[wy * 64 + i * 16][kk], 24);
#pragma unroll
                for (int e = 0; e < af[i].num_elements; e++)
                    af[i].x[e] = wmma::__float_to_tf32(af[i].x[e]);
            }
#pragma unroll
            for (int j = 0; j < 2; j++) {
                wmma::load_matrix_sync(bf[j], &Bs[kk][wx * 32 + j * 16], 136);
#pragma unroll
                for (int e = 0; e < bf[j].num_elements; e++)
                    bf[j].x[e] = wmma::__float_to_tf32(bf[j].x[e]);
            }
#pragma unroll
            for (int i = 0; i < 4; i++)
#pragma unroll
                for (int j = 0; j < 2; j++)
                    wmma::mma_sync(acc[i][j], af[i], bf[j], acc[i][j]);
        }
        __syncthreads();
    }
#pragma unroll
    for (int i = 0; i < 4; i++)
#pragma unroll
        for (int j = 0; j < 2; j++)
            wmma::store_matrix_sync(C + (m0 + wy * 64 + i * 16) * ldc + n0 + wx * 32 + j * 16,
                                    acc[i][j], ldc, wmma::mem_row_major);
}

// ---------------- CSR gather-aggregate + bias + relu (no atomics) ----------------
// H[node] = relu( z[node]*dinv^2 + sum_in z[src]*coef + bias ).  Z has stride ZS.
template<int F, int HS>
__global__ void __launch_bounds__(256)
k_gather(const float* __restrict__ bias, float* __restrict__ H) {
    constexpr int F4 = F / 4;
    constexpr int ZS4 = ZS / 4;
    constexpr int NR = (F4 + 31) / 32;
    int node = blockIdx.x * (blockDim.x >> 5) + (threadIdx.x >> 5);
    int lane = threadIdx.x & 31;
    if (node >= NN) return;

    float d = g_dinv[node], dd = d * d;
    const float4* z4 = (const float4*)g_z;

    float4 acc[NR];
#pragma unroll
    for (int r = 0; r < NR; r++) {
        int f = lane + 32 * r;
        if (f < F4) {
            float4 v = z4[(size_t)node * ZS4 + f];
            acc[r] = make_float4(v.x * dd, v.y * dd, v.z * dd, v.w * dd);
        } else acc[r] = make_float4(0.f, 0.f, 0.f, 0.f);
    }

    int beg = g_off[node], end = beg + g_degi[node];
    for (int e = beg; e < end; e++) {
        int s = g_esrc[e];
        float c = g_ecoef[e];
        const float4* zs = z4 + (size_t)s * ZS4;
#pragma unroll
        for (int r = 0; r < NR; r++) {
            int f = lane + 32 * r;
            if (f < F4) {
                float4 v = zs[f];
                acc[r].x += v.x * c;
                acc[r].y += v.y * c;
                acc[r].z += v.z * c;
                acc[r].w += v.w * c;
            }
        }
    }

    float4* h4 = (float4*)H;
    const float4* b4 = (const float4*)bias;
#pragma unroll
    for (int r = 0; r < NR; r++) {
        int f = lane + 32 * r;
        if (f < F4) {
            float4 b = b4[f];
            h4[(size_t)node * (HS / 4) + f] = make_float4(
                fmaxf(acc[r].x + b.x, 0.f), fmaxf(acc[r].y + b.y, 0.f),
                fmaxf(acc[r].z + b.z, 0.f), fmaxf(acc[r].w + b.w, 0.f));
        }
    }
}

// ---------------- graph max-pool (uint atomicMax valid for >=0 floats) ----------------
__global__ void k_zero_gmax() {
    int i = blockIdx.x * blockDim.x + threadIdx.x;
    if (i < NG * 300) g_gmax[i] = 0.f;   // values are >=0 post-ReLU
}
__global__ void k_segmax(const void* __restrict__ batch) {
    int i = blockIdx.x * blockDim.x + threadIdx.x;
    if (i < NN * 300) {
        int n = i / 300, f = i - n * 300;
        int b = IDX(batch, n, g_is64);
        atomicMax((unsigned int*)&g_gmax[b * 300 + f], __float_as_uint(g_h3[i]));
    }
}

// ---------------- MLP head ----------------
__global__ void k_mlp(const float* __restrict__ W, const float* __restrict__ b,
                      int sel, int M, int N, int K) {
    const float* __restrict__ A = (sel == 0) ? g_gmax : g_m1;
    float* __restrict__ C       = (sel == 0) ? g_m1   : g_m2;
    int i = blockIdx.x * blockDim.x + threadIdx.x;
    if (i < M * N) {
        int m = i / N, n = i - m * N;
        float acc = b[n];
        const float* ar = A + (size_t)m * K;
#pragma unroll 4
        for (int k = 0; k < K; k++) acc += ar[k] * W[(size_t)k * N + n];
        C[i] = fmaxf(acc, 0.f);
    }
}

// logits = m2 @ Wl3 + bl3, then softmax over graph axis (axis 0, per column)
__global__ void k_final(const float* __restrict__ Wl3, const float* __restrict__ bl3,
                        float* __restrict__ out) {
    __shared__ float sl[NG * 6];
    __shared__ float smax[6], ssum[6];
    int t = threadIdx.x;  // 256 threads, one per graph
    float acc[6];
#pragma unroll
    for (int j = 0; j < 6; j++) acc[j] = bl3[j];
    const float* mr = &g_m2[t * 100];
    for (int k = 0; k < 100; k++) {
        float a = mr[k];
#pragma unroll
        for (int j = 0; j < 6; j++) acc[j] += a * Wl3[k * 6 + j];
    }
#pragma unroll
    for (int j = 0; j < 6; j++) sl[t * 6 + j] = acc[j];
    __syncthreads();
    if (t < 6) {
        float mx = -3.4e38f;
        for (int r = 0; r < NG; r++) mx = fmaxf(mx, sl[r * 6 + t]);
        float s = 0.f;
        for (int r = 0; r < NG; r++) s += expf(sl[r * 6 + t] - mx);
        smax[t] = mx;
        ssum[t] = s;
    }
    __syncthreads();
#pragma unroll
    for (int j = 0; j < 6; j++)
        out[t * 6 + j] = expf(sl[t * 6 + j] - smax[j]) / ssum[j];
}

// ---------------- launch ----------------
extern "C" void kernel_launch(void* const* d_in, const int* in_sizes, int n_in,
                              void* d_out, int out_size) {
    const float* x     = (const float*)d_in[0];
    const void*  ei    = d_in[1];
    const void*  batch = d_in[2];
    const float* W1  = (const float*)d_in[3];  const float* b1  = (const float*)d_in[4];
    const float* W2  = (const float*)d_in[5];  const float* b2  = (const float*)d_in[6];
    const float* W3  = (const float*)d_in[7];  const float* b3  = (const float*)d_in[8];
    const float* Wl1 = (const float*)d_in[9];  const float* bl1 = (const float*)d_in[10];
    const float* Wl2 = (const float*)d_in[11]; const float* bl2 = (const float*)d_in[12];
    const float* Wl3 = (const float*)d_in[13]; const float* bl3 = (const float*)d_in[14];
    float* out = (float*)d_out;

    float *p_h1, *p_h2, *p_h3, *p_z, *p_w2p, *p_w3p;
    cudaGetSymbolAddress((void**)&p_h1,  g_h1);
    cudaGetSymbolAddress((void**)&p_h2,  g_h2);
    cudaGetSymbolAddress((void**)&p_h3,  g_h3);
    cudaGetSymbolAddress((void**)&p_z,   g_z);
    cudaGetSymbolAddress((void**)&p_w2p, g_w2p);
    cudaGetSymbolAddress((void**)&p_w3p, g_w3p);

    // dtype detect, degree, dinv, CSR build, weight padding
    k_detect<<<1, 32>>>((const long long*)ei);
    k_zero_int<<<(NN + 255) / 256, 256>>>();
    k_deg<<<(NE + 255) / 256, 256>>>(ei);
    k_dinv<<<(NN + 255) / 256, 256>>>();
    k_scan<<<1, 1024>>>();
    k_fill<<<(NE + 255) / 256, 256>>>(ei);
    k_wpad<<<(500 * 400 + 400 * 300 + 255) / 256, 256>>>(W2, W3);

    // layer 1: gather at dim 19, then GEMM(+bias+relu)
    k_gather1<<<(NN * 32 + 255) / 256, 256>>>(x);
    k_gemm1<<<(NN + 31) / 32, 256>>>(W1, b1);

    // layer 2: Z2 = H1 @ W2 (tf32 wmma), then CSR gather + bias + relu -> H2
    {
        dim3 grid(4, MP / 128);
        k_wgemm<<<grid, 256>>>(p_h1, p_w2p, p_z, ZS, 512, ZS, 512);
    }
    k_gather<400, 400><<<(NN * 32 + 255) / 256, 256>>>(b2, p_h2);

    // layer 3: Z3 = H2 @ W3
    {
        dim3 grid(3, MP / 128);
        k_wgemm<<<grid, 256>>>(p_h2, p_w3p, p_z, 400, 384, ZS, 400);
    }
    k_gather<300, 300><<<(NN * 32 + 255) / 256, 256>>>(b3, p_h3);

    // graph max-pool
    k_zero_gmax<<<(NG * 300 + 255) / 256, 256>>>();
    k_segmax<<<(NN * 300 + 255) / 256, 256>>>(batch);

    // MLP head + softmax over graphs
    k_mlp<<<(NG * 200 + 255) / 256, 256>>>(Wl1, bl1, 0, NG, 200, 300);
    k_mlp<<<(NG * 100 + 255) / 256, 256>>>(Wl2, bl2, 1, NG, 100, 200);
    k_final<<<1, 256>>>(Wl3, bl3, out);
}

// round 11
// speedup vs baseline: 2.8798x; 1.1132x over previous
#include <cuda_runtime.h>
#include <math.h>
#include <stdint.h>
#include <mma.h>
using namespace nvcuda;

#define NN 50000
#define NE 800000
#define NG 256

#define MP 50048          // NN padded to 128-tile
#define ZS 512            // Z / H1 column stride (padded)

// ---------------- scratch (static __device__, zero-init, no allocs) ----------------
__device__ int   g_is64;
__device__ int   g_degi[NN];
__device__ int   g_off [NN];
__device__ int   g_cnt [NN];
__device__ int   g_esrc[NE];
__device__ float g_ecoef[NE];
__device__ float g_dinv[NN];
__device__ float g_aggx2[MP * 32];    // layer-1 aggregate, padded K=32 (col19 = 1 for bias)
__device__ float g_h1  [MP * ZS];     // pad rows/cols stay zero-effective
__device__ float g_z   [MP * ZS];     // GEMM output, stride ZS
__device__ float g_h2  [MP * 400];    // pad rows stay zero
__device__ float g_h3  [NN * 300];
__device__ float g_w1p [32 * 512];    // W1 padded + bias row 19
__device__ float g_w2p [512 * 512];   // W2 padded (pad stays zero)
__device__ float g_w3p [400 * 384];   // W3 padded (pad stays zero)
__device__ float g_gmax[NG * 300];
__device__ float g_m1  [NG * 200];
__device__ float g_m2  [NG * 100];

// Index accessor: handles both int32 and int64 index tensors.
__device__ __forceinline__ int IDX(const void* p, long long i, int is64) {
    return is64 ? (int)((const long long*)p)[i] : ((const int*)p)[i];
}

__device__ __forceinline__ void cp16(void* smem, const void* gmem) {
    uint32_t s = (uint32_t)__cvta_generic_to_shared(smem);
    asm volatile("cp.async.cg.shared.global [%0], [%1], 16;" :: "r"(s), "l"(gmem));
}

// ---------------- dtype detection (int32 vs int64 index tensors) ----------------
__global__ void k_detect(const long long* ei) {
    int lane = threadIdx.x;
    int bad = 0;
    for (int i = lane; i < 1024; i += 32) {
        long long v = ei[i];
        if (v < 0 || v >= NN) bad = 1;
    }
    bad = __any_sync(0xffffffffu, bad);
    if (lane == 0) g_is64 = !bad;
}

// ---------------- degree / normalization / CSR build ----------------
__global__ void k_zero_int() {
    int i = blockIdx.x * blockDim.x + threadIdx.x;
    if (i < NN) { g_degi[i] = 0; g_cnt[i] = 0; }
}
__global__ void k_deg(const void* __restrict__ ei) {
    int i = blockIdx.x * blockDim.x + threadIdx.x;
    if (i < NE) {
        int t = IDX(ei, (long long)NE + i, g_is64);   // dst = row 1
        atomicAdd(&g_degi[t], 1);
    }
}
__global__ void k_dinv() {
    int i = blockIdx.x * blockDim.x + threadIdx.x;
    if (i < NN) g_dinv[i] = rsqrtf((float)g_degi[i] + 1.0f);
}
// exclusive prefix sum of g_degi -> g_off (single block, 1024 threads)
__global__ void k_scan() {
    __shared__ int ssum[1024];
    const int CH = (NN + 1023) / 1024;   // 49
    int t = threadIdx.x;
    int base = t * CH;
    int loc = 0;
    for (int i = 0; i < CH; i++) { int n = base + i; if (n < NN) loc += g_degi[n]; }
    ssum[t] = loc;
    __syncthreads();
    for (int off = 1; off < 1024; off <<= 1) {
        int v = (t >= off) ? ssum[t - off] : 0;
        __syncthreads();
        ssum[t] += v;
        __syncthreads();
    }
    int run = (t == 0) ? 0 : ssum[t - 1];
    for (int i = 0; i < CH; i++) {
        int n = base + i;
        if (n < NN) { g_off[n] = run; run += g_degi[n]; }
    }
}
__global__ void k_fill(const void* __restrict__ ei) {
    int e = blockIdx.x * blockDim.x + threadIdx.x;
    if (e < NE) {
        int is64 = g_is64;
        int s = IDX(ei, e, is64);
        int t = IDX(ei, (long long)NE + e, is64);
        int pos = atomicAdd(&g_cnt[t], 1);
        int idx = g_off[t] + pos;
        g_esrc[idx]  = s;
        g_ecoef[idx] = g_dinv[s] * g_dinv[t];
    }
}

// ---------------- weight padding (valid region only; pad stays zero) ----------------
__global__ void k_wpad(const float* __restrict__ W1, const float* __restrict__ b1,
                       const float* __restrict__ W2, const float* __restrict__ W3) {
    int i = blockIdx.x * blockDim.x + threadIdx.x;
    if (i < 500 * 400) { int k = i / 400, n = i - k * 400; g_w2p[k * 512 + n] = W2[i]; }
    if (i < 400 * 300) { int k = i / 300, n = i - k * 300; g_w3p[k * 384 + n] = W3[i]; }
    if (i < 19 * 500)  { int k = i / 500, n = i - k * 500; g_w1p[k * 512 + n] = W1[i]; }
    if (i < 500)       g_w1p[19 * 512 + i] = b1[i];      // bias row (pairs with ones col)
}

// ---------------- layer 1: gather-aggregate at dim 19 (stride-32 padded out) ----------------
__global__ void k_gather1(const float* __restrict__ x) {
    int node = blockIdx.x * (blockDim.x >> 5) + (threadIdx.x >> 5);
    int lane = threadIdx.x & 31;
    if (node >= NN) return;
    float d = g_dinv[node], dd = d * d;
    float acc = 0.f;
    if (lane < 19) acc = x[(size_t)node * 19 + lane] * dd;
    int beg = g_off[node], end = beg + g_degi[node];
    for (int e = beg; e < end; e++) {
        int s = g_esrc[e];
        float c = g_ecoef[e];
        if (lane < 19) acc += x[(size_t)s * 19 + lane] * c;
    }
    if (lane < 19) g_aggx2[(size_t)node * 32 + lane] = acc;
    if (lane == 19) g_aggx2[(size_t)node * 32 + 19] = 1.0f;   // ones col -> bias row of W1p
}

// ---------------- tf32 WMMA GEMM, cp.async double-buffered ----------------
// C[MP x N] = A @ B (all tiles full via padding). BM=BN=128, BK=16,
// 256 threads (8 warps 2x4), warp tile 64x32. Optional fused ReLU.
__global__ void __launch_bounds__(256)
k_wgemm(const float* __restrict__ A, const float* __restrict__ B,
        float* __restrict__ C, int lda, int ldb, int ldc, int K, int relu) {
    __shared__ float As[2][128][24];
    __shared__ float Bs[2][16][136];
    int t = threadIdx.x;
    int warp = t >> 5;
    int wy = warp >> 2;      // 0..1
    int wx = warp & 3;       // 0..3
    size_t m0 = (size_t)blockIdx.y * 128;
    int n0 = blockIdx.x * 128;

    int a_row = t >> 1;            // wait, need 2 f4/thread; use id scheme below
    (void)a_row;

    wmma::fragment<wmma::accumulator, 16, 16, 8, float> acc[4][2];
#pragma unroll
    for (int i = 0; i < 4; i++)
#pragma unroll
        for (int j = 0; j < 2; j++) wmma::fill_fragment(acc[i][j], 0.f);

    const int NS = K / 16;

    auto issue = [&](int s, int buf) {
#pragma unroll
        for (int r = 0; r < 2; r++) {               // A tile 128x16 = 512 float4
            int id = t + r * 256;
            int row = id >> 2, c4 = (id & 3) * 4;
            cp16(&As[buf][row][c4], A + (m0 + row) * lda + s * 16 + c4);
        }
#pragma unroll
        for (int r = 0; r < 2; r++) {               // B tile 16x128 = 512 float4
            int id = t + r * 256;
            int row = id >> 5, c4 = (id & 31) * 4;
            cp16(&Bs[buf][row][c4], B + (size_t)(s * 16 + row) * ldb + n0 + c4);
        }
        asm volatile("cp.async.commit_group;");
    };

    issue(0, 0);
    for (int s = 0; s < NS; s++) {
        int buf = s & 1;
        if (s + 1 < NS) {
            issue(s + 1, buf ^ 1);
            asm volatile("cp.async.wait_group 1;");
        } else {
            asm volatile("cp.async.wait_group 0;");
        }
        __syncthreads();

#pragma unroll
        for (int kk = 0; kk < 16; kk += 8) {
            wmma::fragment<wmma::matrix_a, 16, 16, 8, wmma::precision::tf32, wmma::row_major> af[4];
            wmma::fragment<wmma::matrix_b, 16, 16, 8, wmma::precision::tf32, wmma::row_major> bf[2];
#pragma unroll
            for (int i = 0; i < 4; i++) {
                wmma::load_matrix_sync(af[i], &As[buf][wy * 64 + i * 16][kk], 24);
#pragma unroll
                for (int e = 0; e < af[i].num_elements; e++)
                    af[i].x[e] = wmma::__float_to_tf32(af[i].x[e]);
            }
#pragma unroll
            for (int j = 0; j < 2; j++) {
                wmma::load_matrix_sync(bf[j], &Bs[buf][kk][wx * 32 + j * 16], 136);
#pragma unroll
                for (int e = 0; e < bf[j].num_elements; e++)
                    bf[j].x[e] = wmma::__float_to_tf32(bf[j].x[e]);
            }
#pragma unroll
            for (int i = 0; i < 4; i++)
#pragma unroll
                for (int j = 0; j < 2; j++)
                    wmma::mma_sync(acc[i][j], af[i], bf[j], acc[i][j]);
        }
        __syncthreads();
    }

    if (relu) {
#pragma unroll
        for (int i = 0; i < 4; i++)
#pragma unroll
            for (int j = 0; j < 2; j++)
#pragma unroll
                for (int e = 0; e < acc[i][j].num_elements; e++)
                    acc[i][j].x[e] = fmaxf(acc[i][j].x[e], 0.f);
    }
#pragma unroll
    for (int i = 0; i < 4; i++)
#pragma unroll
        for (int j = 0; j < 2; j++)
            wmma::store_matrix_sync(C + (m0 + wy * 64 + i * 16) * ldc + n0 + wx * 32 + j * 16,
                                    acc[i][j], ldc, wmma::mem_row_major);
}

// ---------------- CSR gather-aggregate + bias + relu (no atomics) ----------------
// H[node] = relu( z[node]*dinv^2 + sum_in z[src]*coef + bias ).  Z has stride ZS.
template<int F, int HS>
__global__ void __launch_bounds__(256)
k_gather(const float* __restrict__ bias, float* __restrict__ H) {
    constexpr int F4 = F / 4;
    constexpr int ZS4 = ZS / 4;
    constexpr int NR = (F4 + 31) / 32;
    int node = blockIdx.x * (blockDim.x >> 5) + (threadIdx.x >> 5);
    int lane = threadIdx.x & 31;
    if (node >= NN) return;

    float d = g_dinv[node], dd = d * d;
    const float4* z4 = (const float4*)g_z;

    float4 acc[NR];
#pragma unroll
    for (int r = 0; r < NR; r++) {
        int f = lane + 32 * r;
        if (f < F4) {
            float4 v = z4[(size_t)node * ZS4 + f];
            acc[r] = make_float4(v.x * dd, v.y * dd, v.z * dd, v.w * dd);
        } else acc[r] = make_float4(0.f, 0.f, 0.f, 0.f);
    }

    int beg = g_off[node], end = beg + g_degi[node];
    for (int e = beg; e < end; e++) {
        int s = g_esrc[e];
        float c = g_ecoef[e];
        const float4* zs = z4 + (size_t)s * ZS4;
#pragma unroll
        for (int r = 0; r < NR; r++) {
            int f = lane + 32 * r;
            if (f < F4) {
                float4 v = zs[f];
                acc[r].x += v.x * c;
                acc[r].y += v.y * c;
                acc[r].z += v.z * c;
                acc[r].w += v.w * c;
            }
        }
    }

    float4* h4 = (float4*)H;
    const float4* b4 = (const float4*)bias;
#pragma unroll
    for (int r = 0; r < NR; r++) {
        int f = lane + 32 * r;
        if (f < F4) {
            float4 b = b4[f];
            h4[(size_t)node * (HS / 4) + f] = make_float4(
                fmaxf(acc[r].x + b.x, 0.f), fmaxf(acc[r].y + b.y, 0.f),
                fmaxf(acc[r].z + b.z, 0.f), fmaxf(acc[r].w + b.w, 0.f));
        }
    }
}

// ---------------- graph max-pool: batch is sorted -> per-graph range reduce ----------------
__global__ void k_segmax(const void* __restrict__ batch) {
    int g = blockIdx.x;           // one block per graph
    int t = threadIdx.x;          // 256 threads
    int is64 = g_is64;
    __shared__ int s_beg, s_end;
    if (t == 0) {
        int lo = 0, hi = NN;
        while (lo < hi) { int mid = (lo + hi) >> 1; if (IDX(batch, mid, is64) < g) lo = mid + 1; else hi = mid; }
        s_beg = lo;
        hi = NN;
        while (lo < hi) { int mid = (lo + hi) >> 1; if (IDX(batch, mid, is64) < g + 1) lo = mid + 1; else hi = mid; }
        s_end = lo;
    }
    __syncthreads();
    int beg = s_beg, end = s_end;
    for (int f = t; f < 300; f += 256) {
        float mx = 0.f;   // values are >=0 post-ReLU
        for (int r = beg; r < end; r++)
            mx = fmaxf(mx, g_h3[(size_t)r * 300 + f]);
        g_gmax[g * 300 + f] = mx;
    }
}

// ---------------- MLP head ----------------
__global__ void k_mlp(const float* __restrict__ W, const float* __restrict__ b,
                      int sel, int M, int N, int K) {
    const float* __restrict__ A = (sel == 0) ? g_gmax : g_m1;
    float* __restrict__ C       = (sel == 0) ? g_m1   : g_m2;
    int i = blockIdx.x * blockDim.x + threadIdx.x;
    if (i < M * N) {
        int m = i / N, n = i - m * N;
        float acc = b[n];
        const float* ar = A + (size_t)m * K;
#pragma unroll 4
        for (int k = 0; k < K; k++) acc += ar[k] * W[(size_t)k * N + n];
        C[i] = fmaxf(acc, 0.f);
    }
}

// logits = m2 @ Wl3 + bl3, then softmax over graph axis (axis 0, per column)
__global__ void k_final(const float* __restrict__ Wl3, const float* __restrict__ bl3,
                        float* __restrict__ out) {
    __shared__ float sl[NG * 6];
    __shared__ float smax[6], ssum[6];
    int t = threadIdx.x;  // 256 threads, one per graph
    float acc[6];
#pragma unroll
    for (int j = 0; j < 6; j++) acc[j] = bl3[j];
    const float* mr = &g_m2[t * 100];
    for (int k = 0; k < 100; k++) {
        float a = mr[k];
#pragma unroll
        for (int j = 0; j < 6; j++) acc[j] += a * Wl3[k * 6 + j];
    }
#pragma unroll
    for (int j = 0; j < 6; j++) sl[t * 6 + j] = acc[j];
    __syncthreads();
    if (t < 6) {
        float mx = -3.4e38f;
        for (int r = 0; r < NG; r++) mx = fmaxf(mx, sl[r * 6 + t]);
        float s = 0.f;
        for (int r = 0; r < NG; r++) s += expf(sl[r * 6 + t] - mx);
        smax[t] = mx;
        ssum[t] = s;
    }
    __syncthreads();
#pragma unroll
    for (int j = 0; j < 6; j++)
        out[t * 6 + j] = expf(sl[t * 6 + j] - smax[j]) / ssum[j];
}

// ---------------- launch ----------------
extern "C" void kernel_launch(void* const* d_in, const int* in_sizes, int n_in,
                              void* d_out, int out_size) {
    const float* x     = (const float*)d_in[0];
    const void*  ei    = d_in[1];
    const void*  batch = d_in[2];
    const float* W1  = (const float*)d_in[3];  const float* b1  = (const float*)d_in[4];
    const float* W2  = (const float*)d_in[5];  const float* b2  = (const float*)d_in[6];
    const float* W3  = (const float*)d_in[7];  const float* b3  = (const float*)d_in[8];
    const float* Wl1 = (const float*)d_in[9];  const float* bl1 = (const float*)d_in[10];
    const float* Wl2 = (const float*)d_in[11]; const float* bl2 = (const float*)d_in[12];
    const float* Wl3 = (const float*)d_in[13]; const float* bl3 = (const float*)d_in[14];
    float* out = (float*)d_out;

    float *p_aggx2, *p_h1, *p_h2, *p_h3, *p_z, *p_w1p, *p_w2p, *p_w3p;
    cudaGetSymbolAddress((void**)&p_aggx2, g_aggx2);
    cudaGetSymbolAddress((void**)&p_h1,  g_h1);
    cudaGetSymbolAddress((void**)&p_h2,  g_h2);
    cudaGetSymbolAddress((void**)&p_h3,  g_h3);
    cudaGetSymbolAddress((void**)&p_z,   g_z);
    cudaGetSymbolAddress((void**)&p_w1p, g_w1p);
    cudaGetSymbolAddress((void**)&p_w2p, g_w2p);
    cudaGetSymbolAddress((void**)&p_w3p, g_w3p);

    // dtype detect, degree, dinv, CSR build, weight padding
    k_detect<<<1, 32>>>((const long long*)ei);
    k_zero_int<<<(NN + 255) / 256, 256>>>();
    k_deg<<<(NE + 255) / 256, 256>>>(ei);
    k_dinv<<<(NN + 255) / 256, 256>>>();
    k_scan<<<1, 1024>>>();
    k_fill<<<(NE + 255) / 256, 256>>>(ei);
    k_wpad<<<(500 * 400 + 255) / 256, 256>>>(W1, b1, W2, W3);

    // layer 1: gather at dim 19 (padded K=32, ones col), tensor GEMM + fused bias/relu
    k_gather1<<<(NN * 32 + 255) / 256, 256>>>(x);
    {
        dim3 grid(4, MP / 128);
        k_wgemm<<<grid, 256>>>(p_aggx2, p_w1p, p_h1, 32, 512, ZS, 32, 1);
    }

    // layer 2: Z2 = H1 @ W2 (tf32 wmma), then CSR gather + bias + relu -> H2
    {
        dim3 grid(4, MP / 128);
        k_wgemm<<<grid, 256>>>(p_h1, p_w2p, p_z, ZS, 512, ZS, 512, 0);
    }
    k_gather<400, 400><<<(NN * 32 + 255) / 256, 256>>>(b2, p_h2);

    // layer 3: Z3 = H2 @ W3
    {
        dim3 grid(3, MP / 128);
        k_wgemm<<<grid, 256>>>(p_h2, p_w3p, p_z, 400, 384, ZS, 400, 0);
    }
    k_gather<300, 300><<<(NN * 32 + 255) / 256, 256>>>(b3, p_h3);

    // graph max-pool (sorted batch -> range reduce, no atomics)
    k_segmax<<<NG, 256>>>(batch);

    // MLP head + softmax over graphs
    k_mlp<<<(NG * 200 + 255) / 256, 256>>>(Wl1, bl1, 0, NG, 200, 300);
    k_mlp<<<(NG * 100 + 255) / 256, 256>>>(Wl2, bl2, 1, NG, 100, 200);
    k_final<<<1, 256>>>(Wl3, bl3, out);
}

// round 12
// speedup vs baseline: 4.8470x; 1.6831x over previous
#include <cuda_runtime.h>
#include <cuda_bf16.h>
#include <math.h>
#include <stdint.h>
#include <mma.h>
using namespace nvcuda;

#define NN 50000
#define NE 800000
#define NG 256

#define MP 50048          // NN padded to 128-tile
#define ZS 512            // Z / H1 column stride (padded)
#define H2S 416           // H2 bf16 stride (400 padded to BK=32 multiple)

// ---------------- scratch (static __device__, zero-init, no allocs) ----------------
__device__ int   g_is64;
__device__ int   g_degi[NN];
__device__ int   g_off [NN];
__device__ int   g_cnt [NN];
__device__ int   g_esrc[NE];
__device__ float g_ecoef[NE];
__device__ float g_dinv[NN];
__device__ __nv_bfloat16 g_aggx2[MP * 32];   // layer-1 aggregate bf16 (col19 = 1 for bias)
__device__ __nv_bfloat16 g_h1b [MP * ZS];    // H1 bf16 (pads zero)
__device__ float g_z   [MP * ZS];            // GEMM output fp32, stride ZS
__device__ __nv_bfloat16 g_h2b [MP * H2S];   // H2 bf16 (pads zero)
__device__ float g_h3  [NN * 300];
__device__ __nv_bfloat16 g_w1p [32 * 512];   // W1 bf16 + bias row 19
__device__ __nv_bfloat16 g_w2p [512 * 512];  // W2 bf16 padded
__device__ __nv_bfloat16 g_w3p [416 * 384];  // W3 bf16 padded
__device__ float g_gmax[NG * 300];
__device__ float g_m1  [NG * 200];
__device__ float g_m2  [NG * 100];

// Index accessor: handles both int32 and int64 index tensors.
__device__ __forceinline__ int IDX(const void* p, long long i, int is64) {
    return is64 ? (int)((const long long*)p)[i] : ((const int*)p)[i];
}

__device__ __forceinline__ void cp16(void* smem, const void* gmem) {
    uint32_t s = (uint32_t)__cvta_generic_to_shared(smem);
    asm volatile("cp.async.cg.shared.global [%0], [%1], 16;" :: "r"(s), "l"(gmem));
}

// ---------------- dtype detection (int32 vs int64 index tensors) ----------------
__global__ void k_detect(const long long* ei) {
    int lane = threadIdx.x;
    int bad = 0;
    for (int i = lane; i < 1024; i += 32) {
        long long v = ei[i];
        if (v < 0 || v >= NN) bad = 1;
    }
    bad = __any_sync(0xffffffffu, bad);
    if (lane == 0) g_is64 = !bad;
}

// ---------------- degree / normalization / CSR build ----------------
__global__ void k_zero_int() {
    int i = blockIdx.x * blockDim.x + threadIdx.x;
    if (i < NN) { g_degi[i] = 0; g_cnt[i] = 0; }
}
__global__ void k_deg(const void* __restrict__ ei) {
    int i = blockIdx.x * blockDim.x + threadIdx.x;
    if (i < NE) {
        int t = IDX(ei, (long long)NE + i, g_is64);   // dst = row 1
        atomicAdd(&g_degi[t], 1);
    }
}
__global__ void k_dinv() {
    int i = blockIdx.x * blockDim.x + threadIdx.x;
    if (i < NN) g_dinv[i] = rsqrtf((float)g_degi[i] + 1.0f);
}
// exclusive prefix sum of g_degi -> g_off (single block, 1024 threads)
__global__ void k_scan() {
    __shared__ int ssum[1024];
    const int CH = (NN + 1023) / 1024;   // 49
    int t = threadIdx.x;
    int base = t * CH;
    int loc = 0;
    for (int i = 0; i < CH; i++) { int n = base + i; if (n < NN) loc += g_degi[n]; }
    ssum[t] = loc;
    __syncthreads();
    for (int off = 1; off < 1024; off <<= 1) {
        int v = (t >= off) ? ssum[t - off] : 0;
        __syncthreads();
        ssum[t] += v;
        __syncthreads();
    }
    int run = (t == 0) ? 0 : ssum[t - 1];
    for (int i = 0; i < CH; i++) {
        int n = base + i;
        if (n < NN) { g_off[n] = run; run += g_degi[n]; }
    }
}
__global__ void k_fill(const void* __restrict__ ei) {
    int e = blockIdx.x * blockDim.x + threadIdx.x;
    if (e < NE) {
        int is64 = g_is64;
        int s = IDX(ei, e, is64);
        int t = IDX(ei, (long long)NE + e, is64);
        int pos = atomicAdd(&g_cnt[t], 1);
        int idx = g_off[t] + pos;
        g_esrc[idx]  = s;
        g_ecoef[idx] = g_dinv[s] * g_dinv[t];
    }
}

// ---------------- weight padding + bf16 conversion (pads stay zero) ----------------
__global__ void k_wpad(const float* __restrict__ W1, const float* __restrict__ b1,
                       const float* __restrict__ W2, const float* __restrict__ W3) {
    int i = blockIdx.x * blockDim.x + threadIdx.x;
    if (i < 500 * 400) { int k = i / 400, n = i - k * 400; g_w2p[k * 512 + n] = __float2bfloat16(W2[i]); }
    if (i < 400 * 300) { int k = i / 300, n = i - k * 300; g_w3p[k * 384 + n] = __float2bfloat16(W3[i]); }
    if (i < 19 * 500)  { int k = i / 500, n = i - k * 500; g_w1p[k * 512 + n] = __float2bfloat16(W1[i]); }
    if (i < 500)       g_w1p[19 * 512 + i] = __float2bfloat16(b1[i]);   // bias row
}

// ---------------- layer 1: gather-aggregate at dim 19 -> bf16 (stride 32) ----------------
__global__ void k_gather1(const float* __restrict__ x) {
    int node = blockIdx.x * (blockDim.x >> 5) + (threadIdx.x >> 5);
    int lane = threadIdx.x & 31;
    if (node >= NN) return;
    float d = g_dinv[node], dd = d * d;
    float acc = 0.f;
    if (lane < 19) acc = x[(size_t)node * 19 + lane] * dd;
    int beg = g_off[node], end = beg + g_degi[node];
    for (int e = beg; e < end; e++) {
        int s = g_esrc[e];
        float c = g_ecoef[e];
        if (lane < 19) acc += x[(size_t)s * 19 + lane] * c;
    }
    if (lane < 19) g_aggx2[(size_t)node * 32 + lane] = __float2bfloat16(acc);
    if (lane == 19) g_aggx2[(size_t)node * 32 + 19] = __float2bfloat16(1.0f);
}

// ---------------- bf16 WMMA GEMM, cp.async double-buffered ----------------
// C[MP x N] = A @ B. BM=BN=128, BK=32, 256 threads (8 warps 2x4), warp tile 64x32.
// outmode 0: fp32 store to C (ldc=ZS). outmode 1: relu + bf16 store to Hb (stride ZS).
#define AS_LD 40
#define BS_LD 136
__global__ void __launch_bounds__(256)
k_wgemm(const __nv_bfloat16* __restrict__ A, const __nv_bfloat16* __restrict__ B,
        float* __restrict__ C, __nv_bfloat16* __restrict__ Hb,
        int lda, int ldb, int K, int outmode) {
    __shared__ __align__(16) unsigned char sraw[2 * 128 * AS_LD * 2 + 2 * 32 * BS_LD * 2];
    __nv_bfloat16* As = (__nv_bfloat16*)sraw;                          // [2][128][AS_LD]
    __nv_bfloat16* Bs = (__nv_bfloat16*)(sraw + 2 * 128 * AS_LD * 2); // [2][32][BS_LD]

    int t = threadIdx.x;
    int warp = t >> 5;
    int lane = t & 31;
    int wy = warp >> 2;      // 0..1
    int wx = warp & 3;       // 0..3
    size_t m0 = (size_t)blockIdx.y * 128;
    int n0 = blockIdx.x * 128;

    wmma::fragment<wmma::accumulator, 16, 16, 16, float> acc[4][2];
#pragma unroll
    for (int i = 0; i < 4; i++)
#pragma unroll
        for (int j = 0; j < 2; j++) wmma::fill_fragment(acc[i][j], 0.f);

    const int NS = K / 32;

    auto issue = [&](int s, int buf) {
#pragma unroll
        for (int r = 0; r < 2; r++) {               // A tile 128x32 bf16 = 512 x 16B
            int id = t + r * 256;
            int row = id >> 2, c8 = (id & 3) * 8;
            cp16(As + ((buf * 128 + row) * AS_LD + c8),
                 A + (m0 + row) * lda + s * 32 + c8);
        }
#pragma unroll
        for (int r = 0; r < 2; r++) {               // B tile 32x128 bf16 = 512 x 16B
            int id = t + r * 256;
            int row = id >> 4, c8 = (id & 15) * 8;
            cp16(Bs + ((buf * 32 + row) * BS_LD + c8),
                 B + (size_t)(s * 32 + row) * ldb + n0 + c8);
        }
        asm volatile("cp.async.commit_group;");
    };

    issue(0, 0);
    for (int s = 0; s < NS; s++) {
        int buf = s & 1;
        if (s + 1 < NS) {
            issue(s + 1, buf ^ 1);
            asm volatile("cp.async.wait_group 1;");
        } else {
            asm volatile("cp.async.wait_group 0;");
        }
        __syncthreads();

#pragma unroll
        for (int kk = 0; kk < 32; kk += 16) {
            wmma::fragment<wmma::matrix_a, 16, 16, 16, __nv_bfloat16, wmma::row_major> af[4];
            wmma::fragment<wmma::matrix_b, 16, 16, 16, __nv_bfloat16, wmma::row_major> bf[2];
#pragma unroll
            for (int i = 0; i < 4; i++)
                wmma::load_matrix_sync(af[i], As + ((buf * 128 + wy * 64 + i * 16) * AS_LD + kk), AS_LD);
#pragma unroll
            for (int j = 0; j < 2; j++)
                wmma::load_matrix_sync(bf[j], Bs + ((buf * 32 + kk) * BS_LD + wx * 32 + j * 16), BS_LD);
#pragma unroll
            for (int i = 0; i < 4; i++)
#pragma unroll
                for (int j = 0; j < 2; j++)
                    wmma::mma_sync(acc[i][j], af[i], bf[j], acc[i][j]);
        }
        __syncthreads();
    }

    if (outmode == 0) {
#pragma unroll
        for (int i = 0; i < 4; i++)
#pragma unroll
            for (int j = 0; j < 2; j++)
                wmma::store_matrix_sync(C + (m0 + wy * 64 + i * 16) * ZS + n0 + wx * 32 + j * 16,
                                        acc[i][j], ZS, wmma::mem_row_major);
    } else {
        // relu + bf16 store via per-warp smem staging (reuse As region; all loads done)
        float* stg = (float*)sraw + warp * 16 * 20;
#pragma unroll
        for (int i = 0; i < 4; i++)
#pragma unroll
            for (int j = 0; j < 2; j++) {
                wmma::store_matrix_sync(stg, acc[i][j], 20, wmma::mem_row_major);
                __syncwarp();
                int r = lane >> 1, c0 = (lane & 1) * 8;
                union { __nv_bfloat16 b[8]; uint4 u; } pk;
#pragma unroll
                for (int cc = 0; cc < 8; cc++)
                    pk.b[cc] = __float2bfloat16(fmaxf(stg[r * 20 + c0 + cc], 0.f));
                size_t row = m0 + wy * 64 + i * 16 + r;
                int col = n0 + wx * 32 + j * 16 + c0;
                *(uint4*)(Hb + row * ZS + col) = pk.u;
                __syncwarp();
            }
    }
}

// ---------------- CSR gather-aggregate + bias (+relu) ----------------
// acc[node] = z[node]*dinv^2 + sum_in z[src]*coef + bias.  Z fp32 stride ZS.
// OUTBF=1: write bf16 to Hb (stride H2S); else fp32 to H (stride F).
template<int F, int OUTBF>
__global__ void __launch_bounds__(256)
k_gather(const float* __restrict__ bias, float* __restrict__ H, __nv_bfloat16* __restrict__ Hb) {
    constexpr int F4 = F / 4;
    constexpr int ZS4 = ZS / 4;
    constexpr int NR = (F4 + 31) / 32;
    int node = blockIdx.x * (blockDim.x >> 5) + (threadIdx.x >> 5);
    int lane = threadIdx.x & 31;
    if (node >= NN) return;

    float d = g_dinv[node], dd = d * d;
    const float4* z4 = (const float4*)g_z;

    float4 acc[NR];
#pragma unroll
    for (int r = 0; r < NR; r++) {
        int f = lane + 32 * r;
        if (f < F4) {
            float4 v = z4[(size_t)node * ZS4 + f];
            acc[r] = make_float4(v.x * dd, v.y * dd, v.z * dd, v.w * dd);
        } else acc[r] = make_float4(0.f, 0.f, 0.f, 0.f);
    }

    int beg = g_off[node], end = beg + g_degi[node];
    for (int e = beg; e < end; e++) {
        int s = g_esrc[e];
        float c = g_ecoef[e];
        const float4* zs = z4 + (size_t)s * ZS4;
#pragma unroll
        for (int r = 0; r < NR; r++) {
            int f = lane + 32 * r;
            if (f < F4) {
                float4 v = zs[f];
                acc[r].x += v.x * c;
                acc[r].y += v.y * c;
                acc[r].z += v.z * c;
                acc[r].w += v.w * c;
            }
        }
    }

    const float4* b4 = (const float4*)bias;
#pragma unroll
    for (int r = 0; r < NR; r++) {
        int f = lane + 32 * r;
        if (f < F4) {
            float4 b = b4[f];
            float vx = fmaxf(acc[r].x + b.x, 0.f);
            float vy = fmaxf(acc[r].y + b.y, 0.f);
            float vz = fmaxf(acc[r].z + b.z, 0.f);
            float vw = fmaxf(acc[r].w + b.w, 0.f);
            if (OUTBF) {
                union { __nv_bfloat162 h[2]; uint2 u; } pk;
                pk.h[0] = __floats2bfloat162_rn(vx, vy);
                pk.h[1] = __floats2bfloat162_rn(vz, vw);
                *(uint2*)(Hb + (size_t)node * H2S + f * 4) = pk.u;
            } else {
                ((float4*)H)[(size_t)node * F4 + f] = make_float4(vx, vy, vz, vw);
            }
        }
    }
}

// ---------------- graph max-pool: batch is sorted -> per-graph range reduce ----------------
__global__ void k_segmax(const void* __restrict__ batch) {
    int g = blockIdx.x;           // one block per graph
    int t = threadIdx.x;          // 256 threads
    int is64 = g_is64;
    __shared__ int s_beg, s_end;
    if (t == 0) {
        int lo = 0, hi = NN;
        while (lo < hi) { int mid = (lo + hi) >> 1; if (IDX(batch, mid, is64) < g) lo = mid + 1; else hi = mid; }
        s_beg = lo;
        hi = NN;
        while (lo < hi) { int mid = (lo + hi) >> 1; if (IDX(batch, mid, is64) < g + 1) lo = mid + 1; else hi = mid; }
        s_end = lo;
    }
    __syncthreads();
    int beg = s_beg, end = s_end;
    for (int f = t; f < 300; f += 256) {
        float mx = 0.f;   // values are >=0 post-ReLU
        for (int r = beg; r < end; r++)
            mx = fmaxf(mx, g_h3[(size_t)r * 300 + f]);
        g_gmax[g * 300 + f] = mx;
    }
}

// ---------------- MLP head ----------------
__global__ void k_mlp(const float* __restrict__ W, const float* __restrict__ b,
                      int sel, int M, int N, int K) {
    const float* __restrict__ A = (sel == 0) ? g_gmax : g_m1;
    float* __restrict__ C       = (sel == 0) ? g_m1   : g_m2;
    int i = blockIdx.x * blockDim.x + threadIdx.x;
    if (i < M * N) {
        int m = i / N, n = i - m * N;
        float acc = b[n];
        const float* ar = A + (size_t)m * K;
#pragma unroll 4
        for (int k = 0; k < K; k++) acc += ar[k] * W[(size_t)k * N + n];
        C[i] = fmaxf(acc, 0.f);
    }
}

// logits = m2 @ Wl3 + bl3, then softmax over graph axis (axis 0, per column)
__global__ void k_final(const float* __restrict__ Wl3, const float* __restrict__ bl3,
                        float* __restrict__ out) {
    __shared__ float sl[NG * 6];
    __shared__ float smax[6], ssum[6];
    int t = threadIdx.x;  // 256 threads, one per graph
    float acc[6];
#pragma unroll
    for (int j = 0; j < 6; j++) acc[j] = bl3[j];
    const float* mr = &g_m2[t * 100];
    for (int k = 0; k < 100; k++) {
        float a = mr[k];
#pragma unroll
        for (int j = 0; j < 6; j++) acc[j] += a * Wl3[k * 6 + j];
    }
#pragma unroll
    for (int j = 0; j < 6; j++) sl[t * 6 + j] = acc[j];
    __syncthreads();
    if (t < 6) {
        float mx = -3.4e38f;
        for (int r = 0; r < NG; r++) mx = fmaxf(mx, sl[r * 6 + t]);
        float s = 0.f;
        for (int r = 0; r < NG; r++) s += expf(sl[r * 6 + t] - mx);
        smax[t] = mx;
        ssum[t] = s;
    }
    __syncthreads();
#pragma unroll
    for (int j = 0; j < 6; j++)
        out[t * 6 + j] = expf(sl[t * 6 + j] - smax[j]) / ssum[j];
}

// ---------------- launch ----------------
extern "C" void kernel_launch(void* const* d_in, const int* in_sizes, int n_in,
                              void* d_out, int out_size) {
    const float* x     = (const float*)d_in[0];
    const void*  ei    = d_in[1];
    const void*  batch = d_in[2];
    const float* W1  = (const float*)d_in[3];  const float* b1  = (const float*)d_in[4];
    const float* W2  = (const float*)d_in[5];  const float* b2  = (const float*)d_in[6];
    const float* W3  = (const float*)d_in[7];  const float* b3  = (const float*)d_in[8];
    const float* Wl1 = (const float*)d_in[9];  const float* bl1 = (const float*)d_in[10];
    const float* Wl2 = (const float*)d_in[11]; const float* bl2 = (const float*)d_in[12];
    const float* Wl3 = (const float*)d_in[13]; const float* bl3 = (const float*)d_in[14];
    float* out = (float*)d_out;

    __nv_bfloat16 *p_aggx2, *p_h1b, *p_h2b, *p_w1p, *p_w2p, *p_w3p;
    float *p_h3, *p_z;
    cudaGetSymbolAddress((void**)&p_aggx2, g_aggx2);
    cudaGetSymbolAddress((void**)&p_h1b, g_h1b);
    cudaGetSymbolAddress((void**)&p_h2b, g_h2b);
    cudaGetSymbolAddress((void**)&p_h3,  g_h3);
    cudaGetSymbolAddress((void**)&p_z,   g_z);
    cudaGetSymbolAddress((void**)&p_w1p, g_w1p);
    cudaGetSymbolAddress((void**)&p_w2p, g_w2p);
    cudaGetSymbolAddress((void**)&p_w3p, g_w3p);

    // dtype detect, degree, dinv, CSR build, weight padding
    k_detect<<<1, 32>>>((const long long*)ei);
    k_zero_int<<<(NN + 255) / 256, 256>>>();
    k_deg<<<(NE + 255) / 256, 256>>>(ei);
    k_dinv<<<(NN + 255) / 256, 256>>>();
    k_scan<<<1, 1024>>>();
    k_fill<<<(NE + 255) / 256, 256>>>(ei);
    k_wpad<<<(500 * 400 + 255) / 256, 256>>>(W1, b1, W2, W3);

    // layer 1: gather at dim 19 (bf16, ones col), bf16 GEMM + fused bias/relu -> H1 bf16
    k_gather1<<<(NN * 32 + 255) / 256, 256>>>(x);
    {
        dim3 grid(4, MP / 128);
        k_wgemm<<<grid, 256>>>(p_aggx2, p_w1p, p_z, p_h1b, 32, 512, 32, 1);
    }

    // layer 2: Z2 = H1 @ W2 (bf16), CSR gather + bias + relu -> H2 bf16
    {
        dim3 grid(4, MP / 128);
        k_wgemm<<<grid, 256>>>(p_h1b, p_w2p, p_z, (__nv_bfloat16*)0, ZS, 512, 512, 0);
    }
    k_gather<400, 1><<<(NN * 32 + 255) / 256, 256>>>(b2, (float*)0, p_h2b);

    // layer 3: Z3 = H2 @ W3 (bf16, K=416), gather -> H3 fp32
    {
        dim3 grid(3, MP / 128);
        k_wgemm<<<grid, 256>>>(p_h2b, p_w3p, p_z, (__nv_bfloat16*)0, H2S, 384, 416, 0);
    }
    k_gather<300, 0><<<(NN * 32 + 255) / 256, 256>>>(b3, p_h3, (__nv_bfloat16*)0);

    // graph max-pool (sorted batch -> range reduce, no atomics)
    k_segmax<<<NG, 256>>>(batch);

    // MLP head + softmax over graphs
    k_mlp<<<(NG * 200 + 255) / 256, 256>>>(Wl1, bl1, 0, NG, 200, 300);
    k_mlp<<<(NG * 100 + 255) / 256, 256>>>(Wl2, bl2, 1, NG, 100, 200);
    k_final<<<1, 256>>>(Wl3, bl3, out);
}

// round 13
// speedup vs baseline: 5.2441x; 1.0819x over previous
#include <cuda_runtime.h>
#include <cuda_bf16.h>
#include <math.h>
#include <stdint.h>
#include <mma.h>
using namespace nvcuda;

#define NN 50000
#define NE 800000
#define NG 256

#define MP 50048          // NN padded to 128-tile
#define ZS 512            // H1 / Z column stride (padded)
#define H2S 416           // H2 bf16 stride (400 padded to BK=32 multiple)

// ---------------- scratch (static __device__, zero-init, no allocs) ----------------
__device__ int   g_is64;
__device__ int   g_degi[NN];
__device__ int   g_off [NN];
__device__ int   g_cnt [NN];
__device__ int   g_esrc[NE];
__device__ float g_ecoef[NE];
__device__ float g_dinv[NN];
__device__ __nv_bfloat16 g_aggx2[MP * 32];   // layer-1 aggregate bf16 (col19 = 1 for bias)
__device__ __nv_bfloat16 g_h1b [MP * ZS];    // H1 bf16 (pads zero)
__device__ __nv_bfloat16 g_zb  [MP * ZS];    // GEMM output bf16, stride ZS
__device__ __nv_bfloat16 g_h2b [MP * H2S];   // H2 bf16 (pads zero)
__device__ float g_h3  [NN * 300];
__device__ __nv_bfloat16 g_w1p [32 * 512];   // W1 bf16 + bias row 19
__device__ __nv_bfloat16 g_w2p [512 * 512];  // W2 bf16 padded
__device__ __nv_bfloat16 g_w3p [416 * 384];  // W3 bf16 padded
__device__ float g_gmax[NG * 300];
__device__ float g_m1  [NG * 200];
__device__ float g_m2  [NG * 100];

// Index accessor: handles both int32 and int64 index tensors.
__device__ __forceinline__ int IDX(const void* p, long long i, int is64) {
    return is64 ? (int)((const long long*)p)[i] : ((const int*)p)[i];
}

__device__ __forceinline__ void cp16(void* smem, const void* gmem) {
    uint32_t s = (uint32_t)__cvta_generic_to_shared(smem);
    asm volatile("cp.async.cg.shared.global [%0], [%1], 16;" :: "r"(s), "l"(gmem));
}

// ---------------- dtype detection (int32 vs int64 index tensors) ----------------
__global__ void k_detect(const long long* ei) {
    int lane = threadIdx.x;
    int bad = 0;
    for (int i = lane; i < 1024; i += 32) {
        long long v = ei[i];
        if (v < 0 || v >= NN) bad = 1;
    }
    bad = __any_sync(0xffffffffu, bad);
    if (lane == 0) g_is64 = !bad;
}

// ---------------- degree / normalization / CSR build ----------------
__global__ void k_zero_int() {
    int i = blockIdx.x * blockDim.x + threadIdx.x;
    if (i < NN) { g_degi[i] = 0; g_cnt[i] = 0; }
}
__global__ void k_deg(const void* __restrict__ ei) {
    int i = blockIdx.x * blockDim.x + threadIdx.x;
    if (i < NE) {
        int t = IDX(ei, (long long)NE + i, g_is64);   // dst = row 1
        atomicAdd(&g_degi[t], 1);
    }
}
__global__ void k_dinv() {
    int i = blockIdx.x * blockDim.x + threadIdx.x;
    if (i < NN) g_dinv[i] = rsqrtf((float)g_degi[i] + 1.0f);
}
// exclusive prefix sum of g_degi -> g_off (single block, 1024 threads)
__global__ void k_scan() {
    __shared__ int ssum[1024];
    const int CH = (NN + 1023) / 1024;   // 49
    int t = threadIdx.x;
    int base = t * CH;
    int loc = 0;
    for (int i = 0; i < CH; i++) { int n = base + i; if (n < NN) loc += g_degi[n]; }
    ssum[t] = loc;
    __syncthreads();
    for (int off = 1; off < 1024; off <<= 1) {
        int v = (t >= off) ? ssum[t - off] : 0;
        __syncthreads();
        ssum[t] += v;
        __syncthreads();
    }
    int run = (t == 0) ? 0 : ssum[t - 1];
    for (int i = 0; i < CH; i++) {
        int n = base + i;
        if (n < NN) { g_off[n] = run; run += g_degi[n]; }
    }
}
__global__ void k_fill(const void* __restrict__ ei) {
    int e = blockIdx.x * blockDim.x + threadIdx.x;
    if (e < NE) {
        int is64 = g_is64;
        int s = IDX(ei, e, is64);
        int t = IDX(ei, (long long)NE + e, is64);
        int pos = atomicAdd(&g_cnt[t], 1);
        int idx = g_off[t] + pos;
        g_esrc[idx]  = s;
        g_ecoef[idx] = g_dinv[s] * g_dinv[t];
    }
}

// ---------------- weight padding + bf16 conversion (pads stay zero) ----------------
__global__ void k_wpad(const float* __restrict__ W1, const float* __restrict__ b1,
                       const float* __restrict__ W2, const float* __restrict__ W3) {
    int i = blockIdx.x * blockDim.x + threadIdx.x;
    if (i < 500 * 400) { int k = i / 400, n = i - k * 400; g_w2p[k * 512 + n] = __float2bfloat16(W2[i]); }
    if (i < 400 * 300) { int k = i / 300, n = i - k * 300; g_w3p[k * 384 + n] = __float2bfloat16(W3[i]); }
    if (i < 19 * 500)  { int k = i / 500, n = i - k * 500; g_w1p[k * 512 + n] = __float2bfloat16(W1[i]); }
    if (i < 500)       g_w1p[19 * 512 + i] = __float2bfloat16(b1[i]);   // bias row
}

// ---------------- layer 1: gather-aggregate at dim 19 -> bf16 (stride 32) ----------------
__global__ void k_gather1(const float* __restrict__ x) {
    int node = blockIdx.x * (blockDim.x >> 5) + (threadIdx.x >> 5);
    int lane = threadIdx.x & 31;
    if (node >= NN) return;
    float d = g_dinv[node], dd = d * d;
    float acc = 0.f;
    if (lane < 19) acc = x[(size_t)node * 19 + lane] * dd;
    int beg = g_off[node], end = beg + g_degi[node];
    for (int e = beg; e < end; e++) {
        int s = g_esrc[e];
        float c = g_ecoef[e];
        if (lane < 19) acc += x[(size_t)s * 19 + lane] * c;
    }
    if (lane < 19) g_aggx2[(size_t)node * 32 + lane] = __float2bfloat16(acc);
    if (lane == 19) g_aggx2[(size_t)node * 32 + 19] = __float2bfloat16(1.0f);
}

// ---------------- bf16 WMMA GEMM, cp.async double-buffered, bf16 output ----------------
// Hb[MP x N] = (relu?)(A @ B), output bf16 stride ZS. BM=BN=128, BK=32,
// 256 threads (8 warps 2x4), warp tile 64x32.
#define AS_LD 40
#define BS_LD 136
__global__ void __launch_bounds__(256)
k_wgemm(const __nv_bfloat16* __restrict__ A, const __nv_bfloat16* __restrict__ B,
        __nv_bfloat16* __restrict__ Hb, int lda, int ldb, int K, int relu) {
    __shared__ __align__(16) unsigned char sraw[2 * 128 * AS_LD * 2 + 2 * 32 * BS_LD * 2];
    __nv_bfloat16* As = (__nv_bfloat16*)sraw;                          // [2][128][AS_LD]
    __nv_bfloat16* Bs = (__nv_bfloat16*)(sraw + 2 * 128 * AS_LD * 2); // [2][32][BS_LD]

    int t = threadIdx.x;
    int warp = t >> 5;
    int lane = t & 31;
    int wy = warp >> 2;      // 0..1
    int wx = warp & 3;       // 0..3
    size_t m0 = (size_t)blockIdx.y * 128;
    int n0 = blockIdx.x * 128;

    wmma::fragment<wmma::accumulator, 16, 16, 16, float> acc[4][2];
#pragma unroll
    for (int i = 0; i < 4; i++)
#pragma unroll
        for (int j = 0; j < 2; j++) wmma::fill_fragment(acc[i][j], 0.f);

    const int NS = K / 32;

    auto issue = [&](int s, int buf) {
#pragma unroll
        for (int r = 0; r < 2; r++) {               // A tile 128x32 bf16 = 512 x 16B
            int id = t + r * 256;
            int row = id >> 2, c8 = (id & 3) * 8;
            cp16(As + ((buf * 128 + row) * AS_LD + c8),
                 A + (m0 + row) * lda + s * 32 + c8);
        }
#pragma unroll
        for (int r = 0; r < 2; r++) {               // B tile 32x128 bf16 = 512 x 16B
            int id = t + r * 256;
            int row = id >> 4, c8 = (id & 15) * 8;
            cp16(Bs + ((buf * 32 + row) * BS_LD + c8),
                 B + (size_t)(s * 32 + row) * ldb + n0 + c8);
        }
        asm volatile("cp.async.commit_group;");
    };

    issue(0, 0);
    for (int s = 0; s < NS; s++) {
        int buf = s & 1;
        if (s + 1 < NS) {
            issue(s + 1, buf ^ 1);
            asm volatile("cp.async.wait_group 1;");
        } else {
            asm volatile("cp.async.wait_group 0;");
        }
        __syncthreads();

#pragma unroll
        for (int kk = 0; kk < 32; kk += 16) {
            wmma::fragment<wmma::matrix_a, 16, 16, 16, __nv_bfloat16, wmma::row_major> af[4];
            wmma::fragment<wmma::matrix_b, 16, 16, 16, __nv_bfloat16, wmma::row_major> bf[2];
#pragma unroll
            for (int i = 0; i < 4; i++)
                wmma::load_matrix_sync(af[i], As + ((buf * 128 + wy * 64 + i * 16) * AS_LD + kk), AS_LD);
#pragma unroll
            for (int j = 0; j < 2; j++)
                wmma::load_matrix_sync(bf[j], Bs + ((buf * 32 + kk) * BS_LD + wx * 32 + j * 16), BS_LD);
#pragma unroll
            for (int i = 0; i < 4; i++)
#pragma unroll
                for (int j = 0; j < 2; j++)
                    wmma::mma_sync(acc[i][j], af[i], bf[j], acc[i][j]);
        }
        __syncthreads();
    }

    // bf16 (+relu) store via per-warp smem staging (reuse As region; all loads done)
    float* stg = (float*)sraw + warp * 16 * 20;
#pragma unroll
    for (int i = 0; i < 4; i++)
#pragma unroll
        for (int j = 0; j < 2; j++) {
            wmma::store_matrix_sync(stg, acc[i][j], 20, wmma::mem_row_major);
            __syncwarp();
            int r = lane >> 1, c0 = (lane & 1) * 8;
            union { __nv_bfloat16 b[8]; uint4 u; } pk;
            if (relu) {
#pragma unroll
                for (int cc = 0; cc < 8; cc++)
                    pk.b[cc] = __float2bfloat16(fmaxf(stg[r * 20 + c0 + cc], 0.f));
            } else {
#pragma unroll
                for (int cc = 0; cc < 8; cc++)
                    pk.b[cc] = __float2bfloat16(stg[r * 20 + c0 + cc]);
            }
            size_t row = m0 + wy * 64 + i * 16 + r;
            int col = n0 + wx * 32 + j * 16 + c0;
            *(uint4*)(Hb + row * ZS + col) = pk.u;
            __syncwarp();
        }
}

// ---------------- CSR gather-aggregate + bias (+relu), Z in bf16 ----------------
// acc[node] = z[node]*dinv^2 + sum_in z[src]*coef + bias.  Zb bf16 stride ZS.
// OUTBF=1: write bf16 to Hb (stride H2S); else fp32 to H (stride F).
template<int F, int OUTBF>
__global__ void __launch_bounds__(256)
k_gather(const float* __restrict__ bias, float* __restrict__ H, __nv_bfloat16* __restrict__ Hb) {
    constexpr int F4 = F / 4;                 // 100 / 75
    constexpr int NR = (F4 + 31) / 32;        // 4 / 3
    int node = blockIdx.x * (blockDim.x >> 5) + (threadIdx.x >> 5);
    int lane = threadIdx.x & 31;
    if (node >= NN) return;

    float d = g_dinv[node], dd = d * d;
    const uint2* z2 = (const uint2*)g_zb;     // 4 bf16 per uint2
    constexpr int ZR = ZS / 4;                // uint2 per row

    float4 acc[NR];
#pragma unroll
    for (int r = 0; r < NR; r++) {
        int f = lane + 32 * r;
        if (f < F4) {
            uint2 u = z2[(size_t)node * ZR + f];
            float2 lo = __bfloat1622float2(*(__nv_bfloat162*)&u.x);
            float2 hi = __bfloat1622float2(*(__nv_bfloat162*)&u.y);
            acc[r] = make_float4(lo.x * dd, lo.y * dd, hi.x * dd, hi.y * dd);
        } else acc[r] = make_float4(0.f, 0.f, 0.f, 0.f);
    }

    int beg = g_off[node], end = beg + g_degi[node];
    for (int e = beg; e < end; e++) {
        int s = g_esrc[e];
        float c = g_ecoef[e];
        const uint2* zs = z2 + (size_t)s * ZR;
#pragma unroll
        for (int r = 0; r < NR; r++) {
            int f = lane + 32 * r;
            if (f < F4) {
                uint2 u = zs[f];
                float2 lo = __bfloat1622float2(*(__nv_bfloat162*)&u.x);
                float2 hi = __bfloat1622float2(*(__nv_bfloat162*)&u.y);
                acc[r].x = fmaf(lo.x, c, acc[r].x);
                acc[r].y = fmaf(lo.y, c, acc[r].y);
                acc[r].z = fmaf(hi.x, c, acc[r].z);
                acc[r].w = fmaf(hi.y, c, acc[r].w);
            }
        }
    }

    const float4* b4 = (const float4*)bias;
#pragma unroll
    for (int r = 0; r < NR; r++) {
        int f = lane + 32 * r;
        if (f < F4) {
            float4 b = b4[f];
            float vx = fmaxf(acc[r].x + b.x, 0.f);
            float vy = fmaxf(acc[r].y + b.y, 0.f);
            float vz = fmaxf(acc[r].z + b.z, 0.f);
            float vw = fmaxf(acc[r].w + b.w, 0.f);
            if (OUTBF) {
                union { __nv_bfloat162 h[2]; uint2 u; } pk;
                pk.h[0] = __floats2bfloat162_rn(vx, vy);
                pk.h[1] = __floats2bfloat162_rn(vz, vw);
                *(uint2*)(Hb + (size_t)node * H2S + f * 4) = pk.u;
            } else {
                ((float4*)H)[(size_t)node * F4 + f] = make_float4(vx, vy, vz, vw);
            }
        }
    }
}

// ---------------- graph max-pool: batch is sorted -> per-graph range reduce ----------------
__global__ void k_segmax(const void* __restrict__ batch) {
    int g = blockIdx.x;           // one block per graph
    int t = threadIdx.x;          // 256 threads
    int is64 = g_is64;
    __shared__ int s_beg, s_end;
    if (t == 0) {
        int lo = 0, hi = NN;
        while (lo < hi) { int mid = (lo + hi) >> 1; if (IDX(batch, mid, is64) < g) lo = mid + 1; else hi = mid; }
        s_beg = lo;
        hi = NN;
        while (lo < hi) { int mid = (lo + hi) >> 1; if (IDX(batch, mid, is64) < g + 1) lo = mid + 1; else hi = mid; }
        s_end = lo;
    }
    __syncthreads();
    int beg = s_beg, end = s_end;
    for (int f = t; f < 300; f += 256) {
        float mx = 0.f;   // values are >=0 post-ReLU
        for (int r = beg; r < end; r++)
            mx = fmaxf(mx, g_h3[(size_t)r * 300 + f]);
        g_gmax[g * 300 + f] = mx;
    }
}

// ---------------- MLP head ----------------
__global__ void k_mlp(const float* __restrict__ W, const float* __restrict__ b,
                      int sel, int M, int N, int K) {
    const float* __restrict__ A = (sel == 0) ? g_gmax : g_m1;
    float* __restrict__ C       = (sel == 0) ? g_m1   : g_m2;
    int i = blockIdx.x * blockDim.x + threadIdx.x;
    if (i < M * N) {
        int m = i / N, n = i - m * N;
        float acc = b[n];
        const float* ar = A + (size_t)m * K;
#pragma unroll 4
        for (int k = 0; k < K; k++) acc += ar[k] * W[(size_t)k * N + n];
        C[i] = fmaxf(acc, 0.f);
    }
}

// logits = m2 @ Wl3 + bl3, then softmax over graph axis (axis 0, per column)
__global__ void k_final(const float* __restrict__ Wl3, const float* __restrict__ bl3,
                        float* __restrict__ out) {
    __shared__ float sl[NG * 6];
    __shared__ float smax[6], ssum[6];
    int t = threadIdx.x;  // 256 threads, one per graph
    float acc[6];
#pragma unroll
    for (int j = 0; j < 6; j++) acc[j] = bl3[j];
    const float* mr = &g_m2[t * 100];
    for (int k = 0; k < 100; k++) {
        float a = mr[k];
#pragma unroll
        for (int j = 0; j < 6; j++) acc[j] += a * Wl3[k * 6 + j];
    }
#pragma unroll
    for (int j = 0; j < 6; j++) sl[t * 6 + j] = acc[j];
    __syncthreads();
    if (t < 6) {
        float mx = -3.4e38f;
        for (int r = 0; r < NG; r++) mx = fmaxf(mx, sl[r * 6 + t]);
        float s = 0.f;
        for (int r = 0; r < NG; r++) s += expf(sl[r * 6 + t] - mx);
        smax[t] = mx;
        ssum[t] = s;
    }
    __syncthreads();
#pragma unroll
    for (int j = 0; j < 6; j++)
        out[t * 6 + j] = expf(sl[t * 6 + j] - smax[j]) / ssum[j];
}

// ---------------- launch ----------------
extern "C" void kernel_launch(void* const* d_in, const int* in_sizes, int n_in,
                              void* d_out, int out_size) {
    const float* x     = (const float*)d_in[0];
    const void*  ei    = d_in[1];
    const void*  batch = d_in[2];
    const float* W1  = (const float*)d_in[3];  const float* b1  = (const float*)d_in[4];
    const float* W2  = (const float*)d_in[5];  const float* b2  = (const float*)d_in[6];
    const float* W3  = (const float*)d_in[7];  const float* b3  = (const float*)d_in[8];
    const float* Wl1 = (const float*)d_in[9];  const float* bl1 = (const float*)d_in[10];
    const float* Wl2 = (const float*)d_in[11]; const float* bl2 = (const float*)d_in[12];
    const float* Wl3 = (const float*)d_in[13]; const float* bl3 = (const float*)d_in[14];
    float* out = (float*)d_out;

    __nv_bfloat16 *p_aggx2, *p_h1b, *p_h2b, *p_zb, *p_w1p, *p_w2p, *p_w3p;
    float *p_h3;
    cudaGetSymbolAddress((void**)&p_aggx2, g_aggx2);
    cudaGetSymbolAddress((void**)&p_h1b, g_h1b);
    cudaGetSymbolAddress((void**)&p_h2b, g_h2b);
    cudaGetSymbolAddress((void**)&p_h3,  g_h3);
    cudaGetSymbolAddress((void**)&p_zb,  g_zb);
    cudaGetSymbolAddress((void**)&p_w1p, g_w1p);
    cudaGetSymbolAddress((void**)&p_w2p, g_w2p);
    cudaGetSymbolAddress((void**)&p_w3p, g_w3p);

    // dtype detect, degree, dinv, CSR build, weight padding
    k_detect<<<1, 32>>>((const long long*)ei);
    k_zero_int<<<(NN + 255) / 256, 256>>>();
    k_deg<<<(NE + 255) / 256, 256>>>(ei);
    k_dinv<<<(NN + 255) / 256, 256>>>();
    k_scan<<<1, 1024>>>();
    k_fill<<<(NE + 255) / 256, 256>>>(ei);
    k_wpad<<<(500 * 400 + 255) / 256, 256>>>(W1, b1, W2, W3);

    // layer 1: gather at dim 19 (bf16, ones col), bf16 GEMM + fused bias/relu -> H1 bf16
    k_gather1<<<(NN * 32 + 255) / 256, 256>>>(x);
    {
        dim3 grid(4, MP / 128);
        k_wgemm<<<grid, 256>>>(p_aggx2, p_w1p, p_h1b, 32, 512, 32, 1);
    }

    // layer 2: Z2 = H1 @ W2 (bf16 out), CSR gather + bias + relu -> H2 bf16
    {
        dim3 grid(4, MP / 128);
        k_wgemm<<<grid, 256>>>(p_h1b, p_w2p, p_zb, ZS, 512, 512, 0);
    }
    k_gather<400, 1><<<(NN * 32 + 255) / 256, 256>>>(b2, (float*)0, p_h2b);

    // layer 3: Z3 = H2 @ W3 (bf16 out, K=416), gather -> H3 fp32
    {
        dim3 grid(3, MP / 128);
        k_wgemm<<<grid, 256>>>(p_h2b, p_w3p, p_zb, H2S, 384, 416, 0);
    }
    k_gather<300, 0><<<(NN * 32 + 255) / 256, 256>>>(b3, p_h3, (__nv_bfloat16*)0);

    // graph max-pool (sorted batch -> range reduce, no atomics)
    k_segmax<<<NG, 256>>>(batch);

    // MLP head + softmax over graphs
    k_mlp<<<(NG * 200 + 255) / 256, 256>>>(Wl1, bl1, 0, NG, 200, 300);
    k_mlp<<<(NG * 100 + 255) / 256, 256>>>(Wl2, bl2, 1, NG, 100, 200);
    k_final<<<1, 256>>>(Wl3, bl3, out);
}

// round 14
// speedup vs baseline: 5.3206x; 1.0146x over previous
#include <cuda_runtime.h>
#include <cuda_bf16.h>
#include <math.h>
#include <stdint.h>
#include <mma.h>
using namespace nvcuda;

#define NN 50000
#define NE 800000
#define NG 256

#define MP 50048          // NN padded to 128-tile
#define ZS 512            // H1 / Z column stride (padded)
#define H2S 416           // H2 bf16 stride (400 padded to BK=32 multiple)

// ---------------- scratch (static __device__, zero-init, no allocs) ----------------
__device__ int   g_is64;
__device__ int   g_degi[NN];
__device__ int   g_off [NN];
__device__ int   g_cnt [NN];
__device__ int   g_part[256];
__device__ int2  g_edge[NE];                 // packed (src, coef-bits), grouped by dst
__device__ float g_dinv[NN];
__device__ __nv_bfloat16 g_aggx2[MP * 32];   // layer-1 aggregate bf16 (col19 = 1 for bias)
__device__ __nv_bfloat16 g_h1b [MP * ZS];    // H1 bf16 (pads zero)
__device__ __nv_bfloat16 g_zb  [MP * ZS];    // GEMM output bf16, stride ZS
__device__ __nv_bfloat16 g_h2b [MP * H2S];   // H2 bf16 (pads zero)
__device__ float g_h3  [NN * 300];
__device__ __nv_bfloat16 g_w1p [32 * 512];   // W1 bf16 + bias row 19
__device__ __nv_bfloat16 g_w2p [512 * 512];  // W2 bf16 padded
__device__ __nv_bfloat16 g_w3p [416 * 384];  // W3 bf16 padded
__device__ float g_gmax[NG * 300];
__device__ float g_m1  [NG * 200];
__device__ float g_m2  [NG * 100];

// Index accessor: handles both int32 and int64 index tensors.
__device__ __forceinline__ int IDX(const void* p, long long i, int is64) {
    return is64 ? (int)((const long long*)p)[i] : ((const int*)p)[i];
}

__device__ __forceinline__ void cp16(void* smem, const void* gmem) {
    uint32_t s = (uint32_t)__cvta_generic_to_shared(smem);
    asm volatile("cp.async.cg.shared.global [%0], [%1], 16;" :: "r"(s), "l"(gmem));
}

// ---------------- fused: zero deg/cnt + dtype detect ----------------
__global__ void k_detect(const long long* ei) {
    int i = blockIdx.x * blockDim.x + threadIdx.x;
    if (i < NN) { g_degi[i] = 0; g_cnt[i] = 0; }
    if (blockIdx.x == 0 && threadIdx.x < 32) {
        int lane = threadIdx.x;
        int bad = 0;
        for (int k = lane; k < 1024; k += 32) {
            long long v = ei[k];
            if (v < 0 || v >= NN) bad = 1;
        }
        bad = __any_sync(0xffffffffu, bad);
        if (lane == 0) g_is64 = !bad;
    }
}

// ---------------- degree / normalization ----------------
__global__ void k_deg(const void* __restrict__ ei) {
    int i = blockIdx.x * blockDim.x + threadIdx.x;
    if (i < NE) {
        int t = IDX(ei, (long long)NE + i, g_is64);   // dst = row 1
        atomicAdd(&g_degi[t], 1);
    }
}
__global__ void k_dinv() {
    int i = blockIdx.x * blockDim.x + threadIdx.x;
    if (i < NN) g_dinv[i] = rsqrtf((float)g_degi[i] + 1.0f);
}

// ---------------- 3-phase parallel exclusive scan of g_degi -> g_off ----------------
__global__ void k_scan1() {
    __shared__ int s[256];
    int i = blockIdx.x * 256 + threadIdx.x;
    s[threadIdx.x] = (i < NN) ? g_degi[i] : 0;
    __syncthreads();
    for (int o = 128; o > 0; o >>= 1) {
        if (threadIdx.x < o) s[threadIdx.x] += s[threadIdx.x + o];
        __syncthreads();
    }
    if (threadIdx.x == 0) g_part[blockIdx.x] = s[0];
}
__global__ void k_scan2(int nb) {
    __shared__ int s[256];
    int t = threadIdx.x;
    s[t] = (t < nb) ? g_part[t] : 0;
    __syncthreads();
    for (int o = 1; o < 256; o <<= 1) {
        int v = (t >= o) ? s[t - o] : 0;
        __syncthreads();
        s[t] += v;
        __syncthreads();
    }
    if (t < nb) g_part[t] = (t == 0) ? 0 : s[t - 1];
}
__global__ void k_scan3() {
    __shared__ int s[256];
    int i = blockIdx.x * 256 + threadIdx.x;
    int t = threadIdx.x;
    int v = (i < NN) ? g_degi[i] : 0;
    s[t] = v;
    __syncthreads();
    for (int o = 1; o < 256; o <<= 1) {
        int u = (t >= o) ? s[t - o] : 0;
        __syncthreads();
        s[t] += u;
        __syncthreads();
    }
    if (i < NN) g_off[i] = g_part[blockIdx.x] + s[t] - v;   // exclusive
}

__global__ void k_fill(const void* __restrict__ ei) {
    int e = blockIdx.x * blockDim.x + threadIdx.x;
    if (e < NE) {
        int is64 = g_is64;
        int s = IDX(ei, e, is64);
        int t = IDX(ei, (long long)NE + e, is64);
        int pos = atomicAdd(&g_cnt[t], 1);
        float c = g_dinv[s] * g_dinv[t];
        g_edge[g_off[t] + pos] = make_int2(s, __float_as_int(c));
    }
}

// ---------------- weight padding + bf16 conversion (pads stay zero) ----------------
__global__ void k_wpad(const float* __restrict__ W1, const float* __restrict__ b1,
                       const float* __restrict__ W2, const float* __restrict__ W3) {
    int i = blockIdx.x * blockDim.x + threadIdx.x;
    if (i < 500 * 400) { int k = i / 400, n = i - k * 400; g_w2p[k * 512 + n] = __float2bfloat16(W2[i]); }
    if (i < 400 * 300) { int k = i / 300, n = i - k * 300; g_w3p[k * 384 + n] = __float2bfloat16(W3[i]); }
    if (i < 19 * 500)  { int k = i / 500, n = i - k * 500; g_w1p[k * 512 + n] = __float2bfloat16(W1[i]); }
    if (i < 500)       g_w1p[19 * 512 + i] = __float2bfloat16(b1[i]);   // bias row
}

// ---------------- layer 1: gather-aggregate at dim 19 -> bf16 (stride 32) ----------------
__global__ void k_gather1(const float* __restrict__ x) {
    int node = blockIdx.x * (blockDim.x >> 5) + (threadIdx.x >> 5);
    int lane = threadIdx.x & 31;
    if (node >= NN) return;
    float d = g_dinv[node], dd = d * d;
    float acc = 0.f;
    if (lane < 19) acc = x[(size_t)node * 19 + lane] * dd;
    int beg = g_off[node], end = beg + g_degi[node];
    int e = beg;
    for (; e + 2 <= end; e += 2) {
        int2 e0 = g_edge[e], e1 = g_edge[e + 1];
        float v0 = 0.f, v1 = 0.f;
        if (lane < 19) {
            v0 = x[(size_t)e0.x * 19 + lane];
            v1 = x[(size_t)e1.x * 19 + lane];
        }
        acc = fmaf(v0, __int_as_float(e0.y), acc);
        acc = fmaf(v1, __int_as_float(e1.y), acc);
    }
    if (e < end) {
        int2 e0 = g_edge[e];
        if (lane < 19) acc = fmaf(x[(size_t)e0.x * 19 + lane], __int_as_float(e0.y), acc);
    }
    if (lane < 19) g_aggx2[(size_t)node * 32 + lane] = __float2bfloat16(acc);
    if (lane == 19) g_aggx2[(size_t)node * 32 + 19] = __float2bfloat16(1.0f);
}

// ---------------- bf16 WMMA GEMM, cp.async double-buffered, bf16 output ----------------
// Hb[MP x N] = (relu?)(A @ B), output bf16 stride ZS. BM=BN=128, BK=32,
// 256 threads (8 warps 2x4), warp tile 64x32.
#define AS_LD 40
#define BS_LD 136
__global__ void __launch_bounds__(256)
k_wgemm(const __nv_bfloat16* __restrict__ A, const __nv_bfloat16* __restrict__ B,
        __nv_bfloat16* __restrict__ Hb, int lda, int ldb, int K, int relu) {
    __shared__ __align__(16) unsigned char sraw[2 * 128 * AS_LD * 2 + 2 * 32 * BS_LD * 2];
    __nv_bfloat16* As = (__nv_bfloat16*)sraw;                          // [2][128][AS_LD]
    __nv_bfloat16* Bs = (__nv_bfloat16*)(sraw + 2 * 128 * AS_LD * 2); // [2][32][BS_LD]

    int t = threadIdx.x;
    int warp = t >> 5;
    int lane = t & 31;
    int wy = warp >> 2;      // 0..1
    int wx = warp & 3;       // 0..3
    size_t m0 = (size_t)blockIdx.y * 128;
    int n0 = blockIdx.x * 128;

    wmma::fragment<wmma::accumulator, 16, 16, 16, float> acc[4][2];
#pragma unroll
    for (int i = 0; i < 4; i++)
#pragma unroll
        for (int j = 0; j < 2; j++) wmma::fill_fragment(acc[i][j], 0.f);

    const int NS = K / 32;

    auto issue = [&](int s, int buf) {
#pragma unroll
        for (int r = 0; r < 2; r++) {               // A tile 128x32 bf16 = 512 x 16B
            int id = t + r * 256;
            int row = id >> 2, c8 = (id & 3) * 8;
            cp16(As + ((buf * 128 + row) * AS_LD + c8),
                 A + (m0 + row) * lda + s * 32 + c8);
        }
#pragma unroll
        for (int r = 0; r < 2; r++) {               // B tile 32x128 bf16 = 512 x 16B
            int id = t + r * 256;
            int row = id >> 4, c8 = (id & 15) * 8;
            cp16(Bs + ((buf * 32 + row) * BS_LD + c8),
                 B + (size_t)(s * 32 + row) * ldb + n0 + c8);
        }
        asm volatile("cp.async.commit_group;");
    };

    issue(0, 0);
    for (int s = 0; s < NS; s++) {
        int buf = s & 1;
        if (s + 1 < NS) {
            issue(s + 1, buf ^ 1);
            asm volatile("cp.async.wait_group 1;");
        } else {
            asm volatile("cp.async.wait_group 0;");
        }
        __syncthreads();

#pragma unroll
        for (int kk = 0; kk < 32; kk += 16) {
            wmma::fragment<wmma::matrix_a, 16, 16, 16, __nv_bfloat16, wmma::row_major> af[4];
            wmma::fragment<wmma::matrix_b, 16, 16, 16, __nv_bfloat16, wmma::row_major> bf[2];
#pragma unroll
            for (int i = 0; i < 4; i++)
                wmma::load_matrix_sync(af[i], As + ((buf * 128 + wy * 64 + i * 16) * AS_LD + kk), AS_LD);
#pragma unroll
            for (int j = 0; j < 2; j++)
                wmma::load_matrix_sync(bf[j], Bs + ((buf * 32 + kk) * BS_LD + wx * 32 + j * 16), BS_LD);
#pragma unroll
            for (int i = 0; i < 4; i++)
#pragma unroll
                for (int j = 0; j < 2; j++)
                    wmma::mma_sync(acc[i][j], af[i], bf[j], acc[i][j]);
        }
        __syncthreads();
    }

    // bf16 (+relu) store via per-warp smem staging (reuse As region; all loads done)
    float* stg = (float*)sraw + warp * 16 * 20;
#pragma unroll
    for (int i = 0; i < 4; i++)
#pragma unroll
        for (int j = 0; j < 2; j++) {
            wmma::store_matrix_sync(stg, acc[i][j], 20, wmma::mem_row_major);
            __syncwarp();
            int r = lane >> 1, c0 = (lane & 1) * 8;
            union { __nv_bfloat16 b[8]; uint4 u; } pk;
            if (relu) {
#pragma unroll
                for (int cc = 0; cc < 8; cc++)
                    pk.b[cc] = __float2bfloat16(fmaxf(stg[r * 20 + c0 + cc], 0.f));
            } else {
#pragma unroll
                for (int cc = 0; cc < 8; cc++)
                    pk.b[cc] = __float2bfloat16(stg[r * 20 + c0 + cc]);
            }
            size_t row = m0 + wy * 64 + i * 16 + r;
            int col = n0 + wx * 32 + j * 16 + c0;
            *(uint4*)(Hb + row * ZS + col) = pk.u;
            __syncwarp();
        }
}

// ---------------- CSR gather-aggregate + bias (+relu), Z bf16, split warps ----------------
// acc[node] = z[node]*dinv^2 + sum_in z[src]*coef + bias.  SPLIT warps per node,
// each owns PER consecutive uint2 (4-bf16) column groups. Edge loop unrolled x2.
template<int F, int OUTBF, int SPLIT>
__global__ void __launch_bounds__(256)
k_gather(const float* __restrict__ bias, float* __restrict__ H, __nv_bfloat16* __restrict__ Hb) {
    constexpr int F4  = F / 4;                       // uint2 groups per row
    constexpr int PER = (F4 + SPLIT - 1) / SPLIT;    // groups per warp
    constexpr int NR  = (PER + 31) / 32;
    int wid  = blockIdx.x * (blockDim.x >> 5) + (threadIdx.x >> 5);
    int node = wid / SPLIT;
    int part = wid % SPLIT;
    int lane = threadIdx.x & 31;
    if (node >= NN) return;
    int base = part * PER;

    float d = g_dinv[node], dd = d * d;
    const uint2* z2 = (const uint2*)g_zb;
    constexpr int ZR = ZS / 4;

    float4 acc[NR];
#pragma unroll
    for (int r = 0; r < NR; r++) {
        int f = base + lane + 32 * r;
        if (lane + 32 * r < PER && f < F4) {
            uint2 u = z2[(size_t)node * ZR + f];
            float2 lo = __bfloat1622float2(*(__nv_bfloat162*)&u.x);
            float2 hi = __bfloat1622float2(*(__nv_bfloat162*)&u.y);
            acc[r] = make_float4(lo.x * dd, lo.y * dd, hi.x * dd, hi.y * dd);
        } else acc[r] = make_float4(0.f, 0.f, 0.f, 0.f);
    }

    int beg = g_off[node], end = beg + g_degi[node];
    int e = beg;
    for (; e + 2 <= end; e += 2) {
        int2 e0 = g_edge[e], e1 = g_edge[e + 1];
        float c0 = __int_as_float(e0.y), c1 = __int_as_float(e1.y);
        const uint2* za = z2 + (size_t)e0.x * ZR + base;
        const uint2* zb = z2 + (size_t)e1.x * ZR + base;
        uint2 u0[NR], u1[NR];
#pragma unroll
        for (int r = 0; r < NR; r++) {
            int fl = lane + 32 * r;
            if (fl < PER && base + fl < F4) { u0[r] = za[fl]; u1[r] = zb[fl]; }
            else { u0[r] = make_uint2(0, 0); u1[r] = make_uint2(0, 0); }
        }
#pragma unroll
        for (int r = 0; r < NR; r++) {
            float2 lo0 = __bfloat1622float2(*(__nv_bfloat162*)&u0[r].x);
            float2 hi0 = __bfloat1622float2(*(__nv_bfloat162*)&u0[r].y);
            float2 lo1 = __bfloat1622float2(*(__nv_bfloat162*)&u1[r].x);
            float2 hi1 = __bfloat1622float2(*(__nv_bfloat162*)&u1[r].y);
            acc[r].x = fmaf(lo0.x, c0, fmaf(lo1.x, c1, acc[r].x));
            acc[r].y = fmaf(lo0.y, c0, fmaf(lo1.y, c1, acc[r].y));
            acc[r].z = fmaf(hi0.x, c0, fmaf(hi1.x, c1, acc[r].z));
            acc[r].w = fmaf(hi0.y, c0, fmaf(hi1.y, c1, acc[r].w));
        }
    }
    if (e < end) {
        int2 e0 = g_edge[e];
        float c0 = __int_as_float(e0.y);
        const uint2* za = z2 + (size_t)e0.x * ZR + base;
#pragma unroll
        for (int r = 0; r < NR; r++) {
            int fl = lane + 32 * r;
            if (fl < PER && base + fl < F4) {
                uint2 u = za[fl];
                float2 lo = __bfloat1622float2(*(__nv_bfloat162*)&u.x);
                float2 hi = __bfloat1622float2(*(__nv_bfloat162*)&u.y);
                acc[r].x = fmaf(lo.x, c0, acc[r].x);
                acc[r].y = fmaf(lo.y, c0, acc[r].y);
                acc[r].z = fmaf(hi.x, c0, acc[r].z);
                acc[r].w = fmaf(hi.y, c0, acc[r].w);
            }
        }
    }

    const float4* b4 = (const float4*)bias;
#pragma unroll
    for (int r = 0; r < NR; r++) {
        int fl = lane + 32 * r;
        int f = base + fl;
        if (fl < PER && f < F4) {
            float4 b = b4[f];
            float vx = fmaxf(acc[r].x + b.x, 0.f);
            float vy = fmaxf(acc[r].y + b.y, 0.f);
            float vz = fmaxf(acc[r].z + b.z, 0.f);
            float vw = fmaxf(acc[r].w + b.w, 0.f);
            if (OUTBF) {
                union { __nv_bfloat162 h[2]; uint2 u; } pk;
                pk.h[0] = __floats2bfloat162_rn(vx, vy);
                pk.h[1] = __floats2bfloat162_rn(vz, vw);
                *(uint2*)(Hb + (size_t)node * H2S + f * 4) = pk.u;
            } else {
                ((float4*)H)[(size_t)node * F4 + f] = make_float4(vx, vy, vz, vw);
            }
        }
    }
}

// ---------------- graph max-pool: batch is sorted -> per-graph range reduce ----------------
__global__ void k_segmax(const void* __restrict__ batch) {
    int g = blockIdx.x;           // one block per graph
    int t = threadIdx.x;          // 256 threads
    int is64 = g_is64;
    __shared__ int s_beg, s_end;
    if (t == 0) {
        int lo = 0, hi = NN;
        while (lo < hi) { int mid = (lo + hi) >> 1; if (IDX(batch, mid, is64) < g) lo = mid + 1; else hi = mid; }
        s_beg = lo;
        hi = NN;
        while (lo < hi) { int mid = (lo + hi) >> 1; if (IDX(batch, mid, is64) < g + 1) lo = mid + 1; else hi = mid; }
        s_end = lo;
    }
    __syncthreads();
    int beg = s_beg, end = s_end;
    for (int f = t; f < 300; f += 256) {
        float mx = 0.f;   // values are >=0 post-ReLU
        for (int r = beg; r < end; r++)
            mx = fmaxf(mx, g_h3[(size_t)r * 300 + f]);
        g_gmax[g * 300 + f] = mx;
    }
}

// ---------------- MLP head ----------------
__global__ void k_mlp(const float* __restrict__ W, const float* __restrict__ b,
                      int sel, int M, int N, int K) {
    const float* __restrict__ A = (sel == 0) ? g_gmax : g_m1;
    float* __restrict__ C       = (sel == 0) ? g_m1   : g_m2;
    int i = blockIdx.x * blockDim.x + threadIdx.x;
    if (i < M * N) {
        int m = i / N, n = i - m * N;
        float acc = b[n];
        const float* ar = A + (size_t)m * K;
#pragma unroll 4
        for (int k = 0; k < K; k++) acc += ar[k] * W[(size_t)k * N + n];
        C[i] = fmaxf(acc, 0.f);
    }
}

// logits = m2 @ Wl3 + bl3, then softmax over graph axis (axis 0, per column)
__global__ void k_final(const float* __restrict__ Wl3, const float* __restrict__ bl3,
                        float* __restrict__ out) {
    __shared__ float sl[NG * 6];
    __shared__ float smax[6], ssum[6];
    int t = threadIdx.x;  // 256 threads, one per graph
    float acc[6];
#pragma unroll
    for (int j = 0; j < 6; j++) acc[j] = bl3[j];
    const float* mr = &g_m2[t * 100];
    for (int k = 0; k < 100; k++) {
        float a = mr[k];
#pragma unroll
        for (int j = 0; j < 6; j++) acc[j] += a * Wl3[k * 6 + j];
    }
#pragma unroll
    for (int j = 0; j < 6; j++) sl[t * 6 + j] = acc[j];
    __syncthreads();
    if (t < 6) {
        float mx = -3.4e38f;
        for (int r = 0; r < NG; r++) mx = fmaxf(mx, sl[r * 6 + t]);
        float s = 0.f;
        for (int r = 0; r < NG; r++) s += expf(sl[r * 6 + t] - mx);
        smax[t] = mx;
        ssum[t] = s;
    }
    __syncthreads();
#pragma unroll
    for (int j = 0; j < 6; j++)
        out[t * 6 + j] = expf(sl[t * 6 + j] - smax[j]) / ssum[j];
}

// ---------------- launch ----------------
extern "C" void kernel_launch(void* const* d_in, const int* in_sizes, int n_in,
                              void* d_out, int out_size) {
    const float* x     = (const float*)d_in[0];
    const void*  ei    = d_in[1];
    const void*  batch = d_in[2];
    const float* W1  = (const float*)d_in[3];  const float* b1  = (const float*)d_in[4];
    const float* W2  = (const float*)d_in[5];  const float* b2  = (const float*)d_in[6];
    const float* W3  = (const float*)d_in[7];  const float* b3  = (const float*)d_in[8];
    const float* Wl1 = (const float*)d_in[9];  const float* bl1 = (const float*)d_in[10];
    const float* Wl2 = (const float*)d_in[11]; const float* bl2 = (const float*)d_in[12];
    const float* Wl3 = (const float*)d_in[13]; const float* bl3 = (const float*)d_in[14];
    float* out = (float*)d_out;

    __nv_bfloat16 *p_aggx2, *p_h1b, *p_h2b, *p_zb, *p_w1p, *p_w2p, *p_w3p;
    float *p_h3;
    cudaGetSymbolAddress((void**)&p_aggx2, g_aggx2);
    cudaGetSymbolAddress((void**)&p_h1b, g_h1b);
    cudaGetSymbolAddress((void**)&p_h2b, g_h2b);
    cudaGetSymbolAddress((void**)&p_h3,  g_h3);
    cudaGetSymbolAddress((void**)&p_zb,  g_zb);
    cudaGetSymbolAddress((void**)&p_w1p, g_w1p);
    cudaGetSymbolAddress((void**)&p_w2p, g_w2p);
    cudaGetSymbolAddress((void**)&p_w3p, g_w3p);

    const int NB = (NN + 255) / 256;   // 196

    // dtype detect + zero, degree, dinv, parallel scan, edge fill, weight padding
    k_detect<<<NB, 256>>>((const long long*)ei);
    k_deg<<<(NE + 255) / 256, 256>>>(ei);
    k_dinv<<<NB, 256>>>();
    k_scan1<<<NB, 256>>>();
    k_scan2<<<1, 256>>>(NB);
    k_scan3<<<NB, 256>>>();
    k_fill<<<(NE + 255) / 256, 256>>>(ei);
    k_wpad<<<(500 * 400 + 255) / 256, 256>>>(W1, b1, W2, W3);

    // layer 1: gather at dim 19 (bf16, ones col), bf16 GEMM + fused bias/relu -> H1 bf16
    k_gather1<<<(NN * 32 + 255) / 256, 256>>>(x);
    {
        dim3 grid(4, MP / 128);
        k_wgemm<<<grid, 256>>>(p_aggx2, p_w1p, p_h1b, 32, 512, 32, 1);
    }

    // layer 2: Z2 = H1 @ W2 (bf16 out), CSR gather (2 warps/node) -> H2 bf16
    {
        dim3 grid(4, MP / 128);
        k_wgemm<<<grid, 256>>>(p_h1b, p_w2p, p_zb, ZS, 512, 512, 0);
    }
    k_gather<400, 1, 2><<<(NN * 2 * 32 + 255) / 256, 256>>>(b2, (float*)0, p_h2b);

    // layer 3: Z3 = H2 @ W3 (bf16 out, K=416), gather (2 warps/node) -> H3 fp32
    {
        dim3 grid(3, MP / 128);
        k_wgemm<<<grid, 256>>>(p_h2b, p_w3p, p_zb, H2S, 384, 416, 0);
    }
    k_gather<300, 0, 2><<<(NN * 2 * 32 + 255) / 256, 256>>>(b3, p_h3, (__nv_bfloat16*)0);

    // graph max-pool (sorted batch -> range reduce, no atomics)
    k_segmax<<<NG, 256>>>(batch);

    // MLP head + softmax over graphs
    k_mlp<<<(NG * 200 + 255) / 256, 256>>>(Wl1, bl1, 0, NG, 200, 300);
    k_mlp<<<(NG * 100 + 255) / 256, 256>>>(Wl2, bl2, 1, NG, 100, 200);
    k_final<<<1, 256>>>(Wl3, bl3, out);
}